// round 12
// baseline (speedup 1.0000x reference)
#include <cuda_runtime.h>
#include <cuda_bf16.h>
#include <cstdint>
#include <math.h>

// ---------------- problem constants ----------------
#define B_Q     1024
#define DM      4096
#define NH      32
#define NKV     8
#define HD      128
#define PAST    4096
#define SINKS_N 4
#define SCALE_QK 0.08838834764831845f   // 1/sqrt(128)
#define QSCALE   0.12751878662109375f   // fl(SCALE_QK * log2(e))

// ---------------- scratch ----------------
__device__ float g_qbuf[B_Q * NH * HD];
__device__ float g_kbuf[B_Q * NKV * HD];
__device__ float g_vbuf[B_Q * NKV * HD];
__device__ float g_kt[NKV * B_Q * HD];   // tf32-rounded (rope)
__device__ float g_vt[NKV * B_Q * HD];   // tf32-rounded (rope)
__device__ float g_pk[NKV * PAST * HD];  // tf32-rounded past_k
__device__ float g_pv[NKV * PAST * HD];  // tf32-rounded past_v
__device__ float g_attn[B_Q * NH * HD];

// ---------------- helpers ----------------
__device__ __forceinline__ uint32_t smem_u32(const void* p) {
    uint32_t a;
    asm("{ .reg .u64 t; cvta.to.shared.u64 t, %1; cvt.u32.u64 %0, t; }" : "=r"(a) : "l"(p));
    return a;
}
__device__ __forceinline__ unsigned f2tf(float x) {
    unsigned u; asm("cvt.rna.tf32.f32 %0, %1;" : "=r"(u) : "f"(x)); return u;
}
__device__ __forceinline__ float f2tff(float x) { return __uint_as_float(f2tf(x)); }

__device__ __forceinline__ void mma_tf32(float d[4],
    unsigned a0, unsigned a1, unsigned a2, unsigned a3, unsigned b0, unsigned b1)
{
    asm volatile(
        "mma.sync.aligned.m16n8k8.row.col.f32.tf32.tf32.f32 "
        "{%0,%1,%2,%3},{%4,%5,%6,%7},{%8,%9},{%0,%1,%2,%3};"
        : "+f"(d[0]), "+f"(d[1]), "+f"(d[2]), "+f"(d[3])
        : "r"(a0), "r"(a1), "r"(a2), "r"(a3), "r"(b0), "r"(b1));
}
__device__ __forceinline__ void ldm_x4(unsigned a[4], uint32_t addr) {
    asm volatile("ldmatrix.sync.aligned.m8n8.x4.shared.b16 {%0,%1,%2,%3}, [%4];"
        : "=r"(a[0]), "=r"(a[1]), "=r"(a[2]), "=r"(a[3]) : "r"(addr));
}
#define CP16(dst, src) \
    asm volatile("cp.async.cg.shared.global [%0], [%1], 16;" :: "r"(dst), "l"(src) : "memory")
#define CP_COMMIT() asm volatile("cp.async.commit_group;" ::: "memory")
#define CP_WAIT0()  asm volatile("cp.async.wait_group 0;" ::: "memory")

// ---------------- GEMM core (verified R5/R7 version, frozen) ----------------
__device__ __forceinline__ void gemm_core(
    const float* __restrict__ A, const float* __restrict__ B,
    float* __restrict__ C, int N, int K, int m0, int n0, float* smg)
{
    float* As[2] = { smg, smg + 128 * 36 };
    float* Bs[2] = { smg + 2 * 128 * 36, smg + 2 * 128 * 36 + 32 * 132 };

    const int tid  = threadIdx.x;
    const int w    = tid >> 5, lane = tid & 31;
    const int g    = lane >> 2, cq = lane & 3;
    const int wm   = w & 1, wn = w >> 1;

    const int ar  = tid >> 3, ac4 = (tid & 7) * 4;
    const int bkr = tid >> 5, bn4 = (tid & 31) * 4;

    const int lrow = ((lane >> 3) & 1) * 8 + (lane & 7);
    const int lcol = (lane >> 4) * 4;
    int aoff[4];
#pragma unroll
    for (int mt = 0; mt < 4; mt++)
        aoff[mt] = ((wm * 64 + mt * 16 + lrow) * 36 + lcol) * 4;
    const uint32_t as_u[2] = { smem_u32(As[0]), smem_u32(As[1]) };

    float acc[4][4][4];
#pragma unroll
    for (int i = 0; i < 4; i++)
#pragma unroll
        for (int j = 0; j < 4; j++)
#pragma unroll
            for (int r = 0; r < 4; r++) acc[i][j][r] = 0.f;

    const int ns = K >> 5;
    float4 ra[4], rb[4];
#pragma unroll
    for (int p = 0; p < 4; p++) {
        ra[p] = *(const float4*)&A[(size_t)(m0 + ar + p * 32) * K + ac4];
        rb[p] = *(const float4*)&B[(size_t)(bkr + p * 8) * N + n0 + bn4];
    }

    for (int i = 0; i < ns; i++) {
        float* Ab = As[i & 1];
        float* Bb = Bs[i & 1];
        const uint32_t abu = as_u[i & 1];
#pragma unroll
        for (int p = 0; p < 4; p++) {
            *(float4*)&Ab[(ar + p * 32) * 36 + ac4] =
                make_float4(f2tff(ra[p].x), f2tff(ra[p].y), f2tff(ra[p].z), f2tff(ra[p].w));
            *(float4*)&Bb[(bkr + p * 8) * 132 + bn4] =
                make_float4(f2tff(rb[p].x), f2tff(rb[p].y), f2tff(rb[p].z), f2tff(rb[p].w));
        }
        __syncthreads();

        if (i + 1 < ns) {
            const int k0 = (i + 1) * 32;
#pragma unroll
            for (int p = 0; p < 4; p++) {
                ra[p] = *(const float4*)&A[(size_t)(m0 + ar + p * 32) * K + k0 + ac4];
                rb[p] = *(const float4*)&B[(size_t)(k0 + bkr + p * 8) * N + n0 + bn4];
            }
        }

#pragma unroll
        for (int ks = 0; ks < 4; ks++) {
            const int k = ks * 8 + cq;
            unsigned a[4][4], b[4][2];
#pragma unroll
            for (int mt = 0; mt < 4; mt++)
                ldm_x4(a[mt], abu + aoff[mt] + ks * 32);
#pragma unroll
            for (int nt = 0; nt < 4; nt++) {
                int n = wn * 32 + nt * 8 + g;
                b[nt][0] = __float_as_uint(Bb[k * 132 + n]);
                b[nt][1] = __float_as_uint(Bb[(k + 4) * 132 + n]);
            }
#pragma unroll
            for (int mt = 0; mt < 4; mt++)
#pragma unroll
                for (int nt = 0; nt < 4; nt++)
                    mma_tf32(acc[mt][nt], a[mt][0], a[mt][1], a[mt][2], a[mt][3],
                             b[nt][0], b[nt][1]);
        }
    }

#pragma unroll
    for (int mt = 0; mt < 4; mt++)
#pragma unroll
        for (int nt = 0; nt < 4; nt++) {
            int r  = m0 + wm * 64 + mt * 16 + g;
            int cc = n0 + wn * 32 + nt * 8 + 2 * cq;
            *(float2*)&C[(size_t)r * N + cc]       = make_float2(acc[mt][nt][0], acc[mt][nt][1]);
            *(float2*)&C[(size_t)(r + 8) * N + cc] = make_float2(acc[mt][nt][2], acc[mt][nt][3]);
        }
}

__global__ __launch_bounds__(256, 2) void qkv_gemm(
    const float* __restrict__ hidden, const float* __restrict__ Wq,
    const float* __restrict__ Wk, const float* __restrict__ Wv)
{
    extern __shared__ float smg[];
    const int bx = blockIdx.x;
    const float* B; float* C; int N, n0;
    if (bx < 32)      { B = Wq; C = g_qbuf; N = NH * HD;  n0 = bx * 128; }
    else if (bx < 40) { B = Wk; C = g_kbuf; N = NKV * HD; n0 = (bx - 32) * 128; }
    else              { B = Wv; C = g_vbuf; N = NKV * HD; n0 = (bx - 40) * 128; }
    gemm_core(hidden, B, C, N, DM, blockIdx.y * 128, n0, smg);
}

__global__ __launch_bounds__(256, 2) void out_gemm(
    const float* __restrict__ A, const float* __restrict__ Wo, float* __restrict__ C)
{
    extern __shared__ float smg[];
    gemm_core(A, Wo, C, DM, NH * HD, blockIdx.y * 128, blockIdx.x * 128, smg);
}

// ---------------- pre-round past K/V to tf32 values (enables cp.async path) ----------------
__global__ void preround_kernel(const float* __restrict__ pk, const float* __restrict__ pv)
{
    size_t i = ((size_t)blockIdx.x * 256 + threadIdx.x) * 4;
    float4 a = *(const float4*)&pk[i];
    float4 b = *(const float4*)&pv[i];
    *(float4*)&g_pk[i] = make_float4(f2tff(a.x), f2tff(a.y), f2tff(a.z), f2tff(a.w));
    *(float4*)&g_pv[i] = make_float4(f2tff(b.x), f2tff(b.y), f2tff(b.z), f2tff(b.w));
}

// ---------------- RoPE + transpose (K/V only), outputs tf32-rounded ----------------
__global__ void rope_kernel(const float* __restrict__ cosT, const float* __restrict__ sinT)
{
    const int qi   = blockIdx.x;
    const int slot = blockIdx.y;
    const int d    = threadIdx.x;
    const int pos  = PAST + qi;

    if (slot < NKV) {
        const int h = slot;
        const float c = cosT[pos * HD + d];
        const float s = sinT[pos * HD + d];
        const float* src = g_kbuf + (size_t)qi * (NKV * HD) + h * HD;
        float x = src[d], y = src[d ^ 64];
        g_kt[((size_t)h * B_Q + qi) * HD + d] = f2tff(x * c + ((d < 64) ? -y : y) * s);
    } else {
        const int h = slot - NKV;
        g_vt[((size_t)h * B_Q + qi) * HD + d] =
            f2tff(g_vbuf[(size_t)qi * (NKV * HD) + h * HD + d]);
    }
}

// ---------------- Flash attention: cp.async K/V pipeline + tf32 mma ----------------
// 256 threads = 8 warps. Q-tile 128 (warp w owns rows w*16..+15), K-tile 64.
// Q: fused RoPE + scale*log2e, register A-frags. K/V: cp.async double-buffered
// (pre-rounded sources; no register staging, no STS). S B-frags via ldmatrix on
// Ks[key][d]; PV B-frags scalar LDS on Vs[key][d] (R7-verified). exp2 softmax.
// LPT grid: blockIdx.x = head, qtile = 7 - blockIdx.y.
__global__ __launch_bounds__(256) void attn_tc(
    const float* __restrict__ cosT, const float* __restrict__ sinT)
{
    extern __shared__ float sm[];
    float* KsBuf[2] = { sm,                sm + 64 * 132 };
    float* VsBuf[2] = { sm + 2 * 64 * 132, sm + 3 * 64 * 132 };
    float (*Ps)[68] = (float(*)[68])(sm + 4 * 64 * 132);  // 128 x 68

    const int tid = threadIdx.x;
    const int w = tid >> 5, lane = tid & 31;
    const int g = lane >> 2, cq = lane & 3;
    const int h  = blockIdx.x;
    const int q0 = (7 - blockIdx.y) * 128;
    const int kvh = h >> 2;
    const int rbase = w * 16;

    // ---- stage Q with fused RoPE + scale fold (stride 132), ldmatrix -> regs ----
#pragma unroll
    for (int p = 0; p < 16; p++) {
        int e = p * 256 + tid;
        int row = e >> 5, d4 = (e & 31) * 4;
        const float* src = &g_qbuf[(size_t)(q0 + row) * (NH * HD) + h * HD];
        float4 x = *(const float4*)&src[d4];
        float4 y = *(const float4*)&src[d4 ^ 64];
        const int pos = PAST + q0 + row;
        float4 c = *(const float4*)&cosT[pos * HD + d4];
        float4 s = *(const float4*)&sinT[pos * HD + d4];
        float sgn = (d4 < 64) ? -1.f : 1.f;
        float4 r;
        r.x = (x.x * c.x + sgn * y.x * s.x) * QSCALE;
        r.y = (x.y * c.y + sgn * y.y * s.y) * QSCALE;
        r.z = (x.z * c.z + sgn * y.z * s.z) * QSCALE;
        r.w = (x.w * c.w + sgn * y.w * s.w) * QSCALE;
        *(float4*)&sm[row * 132 + d4] =
            make_float4(f2tff(r.x), f2tff(r.y), f2tff(r.z), f2tff(r.w));
    }
    __syncthreads();

    const int lrow = rbase + ((lane >> 3) & 1) * 8 + (lane & 7);
    const int lcol = (lane >> 4) * 4;
    const uint32_t qmat = smem_u32(sm) + (lrow * 132 + lcol) * 4;
    unsigned qf[16][4];
#pragma unroll
    for (int ks = 0; ks < 16; ks++)
        ldm_x4(qf[ks], qmat + ks * 32);
    __syncthreads();   // Q staging reads done before cp.async writes K0/V0

    const uint32_t pmat = smem_u32(&Ps[0][0]) + (lrow * 68 + lcol) * 4;
    const uint32_t ks_u[2] = { smem_u32(KsBuf[0]), smem_u32(KsBuf[1]) };
    const uint32_t vs_u[2] = { smem_u32(VsBuf[0]), smem_u32(VsBuf[1]) };

    // S-loop B-frag ldmatrix bases on Ks
    const int g3 = lane >> 3, l7 = lane & 7;
    uint32_t kmat[2][4];
#pragma unroll
    for (int b = 0; b < 2; b++)
#pragma unroll
        for (int ntp = 0; ntp < 4; ntp++) {
            int row = ntp * 16 + (g3 >> 1) * 8 + l7;
            kmat[b][ntp] = ks_u[b] + (row * 132 + (g3 & 1) * 4) * 4;
        }

    float m_i[2], l_i[2];
    float o[16][4];
    m_i[0] = m_i[1] = -1e30f;
    l_i[0] = l_i[1] = 0.f;
#pragma unroll
    for (int nt = 0; nt < 16; nt++)
#pragma unroll
        for (int r = 0; r < 4; r++) o[nt][r] = 0.f;

    const int ntiles = ((3072 + q0 + 127) >> 6) + 1;
    const int d4c = (lane * 4) & 127;

    // cp.async fill of one K/V tile into buffer BUF (16 x 16B per thread)
#define CP_KV(KT, BUF) do { \
        const int _jb = (KT) * 64; \
        const uint32_t _kb = ks_u[BUF], _vb = vs_u[BUF]; \
        _Pragma("unroll") \
        for (int p = 0; p < 8; p++) { \
            int row = p * 8 + w; \
            int j = _jb + row; \
            int kp = (j < SINKS_N) ? j : j + 1024; \
            const float* _ks; const float* _vs; \
            if (kp < PAST) { \
                size_t off = ((size_t)kvh * PAST + kp) * HD + d4c; \
                _ks = &g_pk[off]; _vs = &g_pv[off]; \
            } else { \
                size_t off = ((size_t)kvh * B_Q + (kp - PAST)) * HD + d4c; \
                _ks = &g_kt[off]; _vs = &g_vt[off]; \
            } \
            uint32_t doff = (uint32_t)(row * 132 + d4c) * 4; \
            CP16(_kb + doff, _ks); \
            CP16(_vb + doff, _vs); \
        } \
    } while (0)

    // prologue: tile 0 -> buffer 0
    CP_KV(0, 0);
    CP_COMMIT();

    for (int kt = 0; kt < ntiles; kt++) {
        const int jbase = kt * 64;
        const int buf = kt & 1;
        const bool pf = (kt + 1 < ntiles);

        CP_WAIT0();        // this thread's copies for `buf` done
        __syncthreads();   // all threads' copies visible; prior readers of buf^1 done

        if (pf) { CP_KV(kt + 1, buf ^ 1); CP_COMMIT(); }   // async prefetch

        // ---- S = Q @ K^T : 16 rows x 64 keys per warp ----
        float s[8][4];
#pragma unroll
        for (int nt = 0; nt < 8; nt++)
#pragma unroll
            for (int r = 0; r < 4; r++) s[nt][r] = 0.f;

#pragma unroll
        for (int ks = 0; ks < 16; ks++) {
#pragma unroll
            for (int ntp = 0; ntp < 4; ntp++) {
                unsigned bf[4];
                ldm_x4(bf, kmat[buf][ntp] + ks * 32);
                mma_tf32(s[2 * ntp],     qf[ks][0], qf[ks][1], qf[ks][2], qf[ks][3], bf[0], bf[1]);
                mma_tf32(s[2 * ntp + 1], qf[ks][0], qf[ks][1], qf[ks][2], qf[ks][3], bf[2], bf[3]);
            }
        }

        // ---- online softmax (base-2 domain, R9-verified) ----
#pragma unroll
        for (int half = 0; half < 2; half++) {
            const int rl  = rbase + g + half * 8;
            const int lim = 3072 + q0 + rl;
            float mx = -1e30f;
#pragma unroll
            for (int nt = 0; nt < 8; nt++)
#pragma unroll
                for (int rr = 0; rr < 2; rr++) {
                    int jg = jbase + nt * 8 + 2 * cq + rr;
                    float v = (jg <= lim) ? s[nt][half * 2 + rr] : -1e30f;
                    s[nt][half * 2 + rr] = v;
                    mx = fmaxf(mx, v);
                }
            mx = fmaxf(mx, __shfl_xor_sync(0xffffffffu, mx, 1));
            mx = fmaxf(mx, __shfl_xor_sync(0xffffffffu, mx, 2));
            float mnew = fmaxf(m_i[half], mx);
            float corr = exp2f(m_i[half] - mnew);
            m_i[half] = mnew;
            float rs = 0.f;
#pragma unroll
            for (int nt = 0; nt < 8; nt++) {
                float p0 = exp2f(s[nt][half * 2]     - mnew);
                float p1 = exp2f(s[nt][half * 2 + 1] - mnew);
                rs += p0 + p1;
                *(float2*)&Ps[rl][nt * 8 + 2 * cq] = make_float2(f2tff(p0), f2tff(p1));
            }
            rs += __shfl_xor_sync(0xffffffffu, rs, 1);
            rs += __shfl_xor_sync(0xffffffffu, rs, 2);
            l_i[half] = l_i[half] * corr + rs;
#pragma unroll
            for (int nt = 0; nt < 16; nt++) {
                o[nt][half * 2]     *= corr;
                o[nt][half * 2 + 1] *= corr;
            }
        }
        __syncwarp();   // Ps is warp-private

        // ---- O += P @ V : 16 rows x 128 d per warp, k-dim 64 (scalar V frags) ----
        const float* Vb = VsBuf[buf];
#pragma unroll
        for (int ks = 0; ks < 8; ks++) {
            const int k = ks * 8 + cq;
            unsigned a[4];
            ldm_x4(a, pmat + ks * 32);
#pragma unroll
            for (int nt = 0; nt < 16; nt++) {
                unsigned b0 = __float_as_uint(Vb[k * 132 + nt * 8 + g]);
                unsigned b1 = __float_as_uint(Vb[(k + 4) * 132 + nt * 8 + g]);
                mma_tf32(o[nt], a[0], a[1], a[2], a[3], b0, b1);
            }
        }
    }

    // ---- epilogue ----
    float inv0 = 1.0f / l_i[0];
    float inv1 = 1.0f / l_i[1];
    int row0 = q0 + rbase + g;
#pragma unroll
    for (int nt = 0; nt < 16; nt++) {
        int dd = nt * 8 + 2 * cq;
        *(float2*)&g_attn[(size_t)row0 * (NH * HD) + h * HD + dd] =
            make_float2(o[nt][0] * inv0, o[nt][1] * inv0);
        *(float2*)&g_attn[(size_t)(row0 + 8) * (NH * HD) + h * HD + dd] =
            make_float2(o[nt][2] * inv1, o[nt][3] * inv1);
    }
}

// ---------------- launch ----------------
extern "C" void kernel_launch(void* const* d_in, const int* in_sizes, int n_in,
                              void* d_out, int out_size)
{
    (void)in_sizes; (void)n_in; (void)out_size;
    const float* hidden = (const float*)d_in[0];
    const float* Wq     = (const float*)d_in[1];
    const float* Wk     = (const float*)d_in[2];
    const float* Wv     = (const float*)d_in[3];
    const float* Wo     = (const float*)d_in[4];
    const float* past_k = (const float*)d_in[5];
    const float* past_v = (const float*)d_in[6];
    const float* cosT   = (const float*)d_in[7];
    const float* sinT   = (const float*)d_in[8];

    void *p_attn;
    cudaGetSymbolAddress(&p_attn, g_attn);

    const int gemm_smem = (2 * 128 * 36 + 2 * 32 * 132) * 4;   // 70656 B
    cudaFuncSetAttribute(qkv_gemm, cudaFuncAttributeMaxDynamicSharedMemorySize, gemm_smem);
    cudaFuncSetAttribute(out_gemm, cudaFuncAttributeMaxDynamicSharedMemorySize, gemm_smem);
    const int attn_smem = (4 * 64 * 132 + 128 * 68) * 4;       // 169984 B
    cudaFuncSetAttribute(attn_tc, cudaFuncAttributeMaxDynamicSharedMemorySize, attn_smem);

    dim3 blk(256);
    preround_kernel<<<(NKV * PAST * HD) / 1024, 256>>>(past_k, past_v);
    qkv_gemm<<<dim3(48, 8), blk, gemm_smem>>>(hidden, Wq, Wk, Wv);
    rope_kernel<<<dim3(B_Q, 2 * NKV), 128>>>(cosT, sinT);
    attn_tc<<<dim3(NH, B_Q / 128), blk, attn_smem>>>(cosT, sinT);
    out_gemm<<<dim3(32, 8), blk, gemm_smem>>>((const float*)p_attn, Wo, (float*)d_out);
}

// round 13
// speedup vs baseline: 1.5214x; 1.5214x over previous
#include <cuda_runtime.h>
#include <cuda_bf16.h>
#include <cstdint>
#include <math.h>

// ---------------- problem constants ----------------
#define B_Q     1024
#define DM      4096
#define NH      32
#define NKV     8
#define HD      128
#define PAST    4096
#define SINKS_N 4
#define SCALE_QK 0.08838834764831845f   // 1/sqrt(128)
#define QSCALE   0.12751878662109375f   // fl(SCALE_QK * log2(e))

// ---------------- scratch ----------------
__device__ float g_qbuf[B_Q * NH * HD];
__device__ float g_kbuf[B_Q * NKV * HD];
__device__ float g_vbuf[B_Q * NKV * HD];
__device__ float g_kt[NKV * B_Q * HD];   // tf32-rounded (rope)
__device__ float g_vt[NKV * B_Q * HD];   // tf32-rounded (rope)
__device__ float g_pk[NKV * PAST * HD];  // tf32-rounded past_k
__device__ float g_pv[NKV * PAST * HD];  // tf32-rounded past_v
__device__ float g_attn[B_Q * NH * HD];

// ---------------- helpers ----------------
__device__ __forceinline__ uint32_t smem_u32(const void* p) {
    uint32_t a;
    asm("{ .reg .u64 t; cvta.to.shared.u64 t, %1; cvt.u32.u64 %0, t; }" : "=r"(a) : "l"(p));
    return a;
}
__device__ __forceinline__ unsigned f2tf(float x) {
    unsigned u; asm("cvt.rna.tf32.f32 %0, %1;" : "=r"(u) : "f"(x)); return u;
}
__device__ __forceinline__ float f2tff(float x) { return __uint_as_float(f2tf(x)); }

__device__ __forceinline__ void mma_tf32(float d[4],
    unsigned a0, unsigned a1, unsigned a2, unsigned a3, unsigned b0, unsigned b1)
{
    asm volatile(
        "mma.sync.aligned.m16n8k8.row.col.f32.tf32.tf32.f32 "
        "{%0,%1,%2,%3},{%4,%5,%6,%7},{%8,%9},{%0,%1,%2,%3};"
        : "+f"(d[0]), "+f"(d[1]), "+f"(d[2]), "+f"(d[3])
        : "r"(a0), "r"(a1), "r"(a2), "r"(a3), "r"(b0), "r"(b1));
}
__device__ __forceinline__ void ldm_x4(unsigned a[4], uint32_t addr) {
    asm volatile("ldmatrix.sync.aligned.m8n8.x4.shared.b16 {%0,%1,%2,%3}, [%4];"
        : "=r"(a[0]), "=r"(a[1]), "=r"(a[2]), "=r"(a[3]) : "r"(addr));
}
#define CP16(dst, src) \
    asm volatile("cp.async.cg.shared.global [%0], [%1], 16;" :: "r"(dst), "l"(src) : "memory")
#define CP_COMMIT() asm volatile("cp.async.commit_group;" ::: "memory")
#define CP_WAIT0()  asm volatile("cp.async.wait_group 0;" ::: "memory")

// ---------------- GEMM core (verified R5/R7 version, frozen) ----------------
__device__ __forceinline__ void gemm_core(
    const float* __restrict__ A, const float* __restrict__ B,
    float* __restrict__ C, int N, int K, int m0, int n0, float* smg)
{
    float* As[2] = { smg, smg + 128 * 36 };
    float* Bs[2] = { smg + 2 * 128 * 36, smg + 2 * 128 * 36 + 32 * 132 };

    const int tid  = threadIdx.x;
    const int w    = tid >> 5, lane = tid & 31;
    const int g    = lane >> 2, cq = lane & 3;
    const int wm   = w & 1, wn = w >> 1;

    const int ar  = tid >> 3, ac4 = (tid & 7) * 4;
    const int bkr = tid >> 5, bn4 = (tid & 31) * 4;

    const int lrow = ((lane >> 3) & 1) * 8 + (lane & 7);
    const int lcol = (lane >> 4) * 4;
    int aoff[4];
#pragma unroll
    for (int mt = 0; mt < 4; mt++)
        aoff[mt] = ((wm * 64 + mt * 16 + lrow) * 36 + lcol) * 4;
    const uint32_t as_u[2] = { smem_u32(As[0]), smem_u32(As[1]) };

    float acc[4][4][4];
#pragma unroll
    for (int i = 0; i < 4; i++)
#pragma unroll
        for (int j = 0; j < 4; j++)
#pragma unroll
            for (int r = 0; r < 4; r++) acc[i][j][r] = 0.f;

    const int ns = K >> 5;
    float4 ra[4], rb[4];
#pragma unroll
    for (int p = 0; p < 4; p++) {
        ra[p] = *(const float4*)&A[(size_t)(m0 + ar + p * 32) * K + ac4];
        rb[p] = *(const float4*)&B[(size_t)(bkr + p * 8) * N + n0 + bn4];
    }

    for (int i = 0; i < ns; i++) {
        float* Ab = As[i & 1];
        float* Bb = Bs[i & 1];
        const uint32_t abu = as_u[i & 1];
#pragma unroll
        for (int p = 0; p < 4; p++) {
            *(float4*)&Ab[(ar + p * 32) * 36 + ac4] =
                make_float4(f2tff(ra[p].x), f2tff(ra[p].y), f2tff(ra[p].z), f2tff(ra[p].w));
            *(float4*)&Bb[(bkr + p * 8) * 132 + bn4] =
                make_float4(f2tff(rb[p].x), f2tff(rb[p].y), f2tff(rb[p].z), f2tff(rb[p].w));
        }
        __syncthreads();

        if (i + 1 < ns) {
            const int k0 = (i + 1) * 32;
#pragma unroll
            for (int p = 0; p < 4; p++) {
                ra[p] = *(const float4*)&A[(size_t)(m0 + ar + p * 32) * K + k0 + ac4];
                rb[p] = *(const float4*)&B[(size_t)(k0 + bkr + p * 8) * N + n0 + bn4];
            }
        }

#pragma unroll
        for (int ks = 0; ks < 4; ks++) {
            const int k = ks * 8 + cq;
            unsigned a[4][4], b[4][2];
#pragma unroll
            for (int mt = 0; mt < 4; mt++)
                ldm_x4(a[mt], abu + aoff[mt] + ks * 32);
#pragma unroll
            for (int nt = 0; nt < 4; nt++) {
                int n = wn * 32 + nt * 8 + g;
                b[nt][0] = __float_as_uint(Bb[k * 132 + n]);
                b[nt][1] = __float_as_uint(Bb[(k + 4) * 132 + n]);
            }
#pragma unroll
            for (int mt = 0; mt < 4; mt++)
#pragma unroll
                for (int nt = 0; nt < 4; nt++)
                    mma_tf32(acc[mt][nt], a[mt][0], a[mt][1], a[mt][2], a[mt][3],
                             b[nt][0], b[nt][1]);
        }
    }

#pragma unroll
    for (int mt = 0; mt < 4; mt++)
#pragma unroll
        for (int nt = 0; nt < 4; nt++) {
            int r  = m0 + wm * 64 + mt * 16 + g;
            int cc = n0 + wn * 32 + nt * 8 + 2 * cq;
            *(float2*)&C[(size_t)r * N + cc]       = make_float2(acc[mt][nt][0], acc[mt][nt][1]);
            *(float2*)&C[(size_t)(r + 8) * N + cc] = make_float2(acc[mt][nt][2], acc[mt][nt][3]);
        }
}

__global__ __launch_bounds__(256, 2) void qkv_gemm(
    const float* __restrict__ hidden, const float* __restrict__ Wq,
    const float* __restrict__ Wk, const float* __restrict__ Wv)
{
    extern __shared__ float smg[];
    const int bx = blockIdx.x;
    const float* B; float* C; int N, n0;
    if (bx < 32)      { B = Wq; C = g_qbuf; N = NH * HD;  n0 = bx * 128; }
    else if (bx < 40) { B = Wk; C = g_kbuf; N = NKV * HD; n0 = (bx - 32) * 128; }
    else              { B = Wv; C = g_vbuf; N = NKV * HD; n0 = (bx - 40) * 128; }
    gemm_core(hidden, B, C, N, DM, blockIdx.y * 128, n0, smg);
}

__global__ __launch_bounds__(256, 2) void out_gemm(
    const float* __restrict__ A, const float* __restrict__ Wo, float* __restrict__ C)
{
    extern __shared__ float smg[];
    gemm_core(A, Wo, C, DM, NH * HD, blockIdx.y * 128, blockIdx.x * 128, smg);
}

// ---------------- pre-round past K/V to tf32 values (enables cp.async path) ----------------
__global__ void preround_kernel(const float* __restrict__ pk, const float* __restrict__ pv)
{
    size_t i = ((size_t)blockIdx.x * 256 + threadIdx.x) * 4;
    float4 a = *(const float4*)&pk[i];
    float4 b = *(const float4*)&pv[i];
    *(float4*)&g_pk[i] = make_float4(f2tff(a.x), f2tff(a.y), f2tff(a.z), f2tff(a.w));
    *(float4*)&g_pv[i] = make_float4(f2tff(b.x), f2tff(b.y), f2tff(b.z), f2tff(b.w));
}

// ---------------- RoPE + transpose (K/V only), outputs tf32-rounded ----------------
__global__ void rope_kernel(const float* __restrict__ cosT, const float* __restrict__ sinT)
{
    const int qi   = blockIdx.x;
    const int slot = blockIdx.y;
    const int d    = threadIdx.x;
    const int pos  = PAST + qi;

    if (slot < NKV) {
        const int h = slot;
        const float c = cosT[pos * HD + d];
        const float s = sinT[pos * HD + d];
        const float* src = g_kbuf + (size_t)qi * (NKV * HD) + h * HD;
        float x = src[d], y = src[d ^ 64];
        g_kt[((size_t)h * B_Q + qi) * HD + d] = f2tff(x * c + ((d < 64) ? -y : y) * s);
    } else {
        const int h = slot - NKV;
        g_vt[((size_t)h * B_Q + qi) * HD + d] =
            f2tff(g_vbuf[(size_t)qi * (NKV * HD) + h * HD + d]);
    }
}

// ---------------- Flash attention: cp.async K/V pipeline + tf32 mma ----------------
// 256 threads = 8 warps. Q-tile 128 (warp w owns rows w*16..+15), K-tile 64.
// Q: fused RoPE + scale*log2e, register A-frags. K/V: cp.async double-buffered
// (pre-rounded sources; no register staging, no STS). S B-frags via ldmatrix on
// Ks[key][d]; PV B-frags scalar LDS on Vs[key][d] (R7-verified). exp2 softmax.
// LPT grid: blockIdx.x = head, qtile = 7 - blockIdx.y.
__global__ __launch_bounds__(256) void attn_tc(
    const float* __restrict__ cosT, const float* __restrict__ sinT)
{
    extern __shared__ float sm[];
    float* KsBuf[2] = { sm,                sm + 64 * 132 };
    float* VsBuf[2] = { sm + 2 * 64 * 132, sm + 3 * 64 * 132 };
    float (*Ps)[68] = (float(*)[68])(sm + 4 * 64 * 132);  // 128 x 68

    const int tid = threadIdx.x;
    const int w = tid >> 5, lane = tid & 31;
    const int g = lane >> 2, cq = lane & 3;
    const int h  = blockIdx.x;
    const int q0 = (7 - blockIdx.y) * 128;
    const int kvh = h >> 2;
    const int rbase = w * 16;

    // ---- stage Q with fused RoPE + scale fold (stride 132), ldmatrix -> regs ----
#pragma unroll
    for (int p = 0; p < 16; p++) {
        int e = p * 256 + tid;
        int row = e >> 5, d4 = (e & 31) * 4;
        const float* src = &g_qbuf[(size_t)(q0 + row) * (NH * HD) + h * HD];
        float4 x = *(const float4*)&src[d4];
        float4 y = *(const float4*)&src[d4 ^ 64];
        const int pos = PAST + q0 + row;
        float4 c = *(const float4*)&cosT[pos * HD + d4];
        float4 s = *(const float4*)&sinT[pos * HD + d4];
        float sgn = (d4 < 64) ? -1.f : 1.f;
        float4 r;
        r.x = (x.x * c.x + sgn * y.x * s.x) * QSCALE;
        r.y = (x.y * c.y + sgn * y.y * s.y) * QSCALE;
        r.z = (x.z * c.z + sgn * y.z * s.z) * QSCALE;
        r.w = (x.w * c.w + sgn * y.w * s.w) * QSCALE;
        *(float4*)&sm[row * 132 + d4] =
            make_float4(f2tff(r.x), f2tff(r.y), f2tff(r.z), f2tff(r.w));
    }
    __syncthreads();

    const int lrow = rbase + ((lane >> 3) & 1) * 8 + (lane & 7);
    const int lcol = (lane >> 4) * 4;
    const uint32_t qmat = smem_u32(sm) + (lrow * 132 + lcol) * 4;
    unsigned qf[16][4];
#pragma unroll
    for (int ks = 0; ks < 16; ks++)
        ldm_x4(qf[ks], qmat + ks * 32);
    __syncthreads();   // Q staging reads done before cp.async writes K0/V0

    const uint32_t pmat = smem_u32(&Ps[0][0]) + (lrow * 68 + lcol) * 4;
    const uint32_t ks_u[2] = { smem_u32(KsBuf[0]), smem_u32(KsBuf[1]) };
    const uint32_t vs_u[2] = { smem_u32(VsBuf[0]), smem_u32(VsBuf[1]) };

    // S-loop B-frag ldmatrix bases on Ks
    const int g3 = lane >> 3, l7 = lane & 7;
    uint32_t kmat[2][4];
#pragma unroll
    for (int b = 0; b < 2; b++)
#pragma unroll
        for (int ntp = 0; ntp < 4; ntp++) {
            int row = ntp * 16 + (g3 >> 1) * 8 + l7;
            kmat[b][ntp] = ks_u[b] + (row * 132 + (g3 & 1) * 4) * 4;
        }

    float m_i[2], l_i[2];
    float o[16][4];
    m_i[0] = m_i[1] = -1e30f;
    l_i[0] = l_i[1] = 0.f;
#pragma unroll
    for (int nt = 0; nt < 16; nt++)
#pragma unroll
        for (int r = 0; r < 4; r++) o[nt][r] = 0.f;

    const int ntiles = ((3072 + q0 + 127) >> 6) + 1;
    const int d4c = (lane * 4) & 127;

    // cp.async fill of one K/V tile into buffer BUF (16 x 16B per thread)
#define CP_KV(KT, BUF) do { \
        const int _jb = (KT) * 64; \
        const uint32_t _kb = ks_u[BUF], _vb = vs_u[BUF]; \
        _Pragma("unroll") \
        for (int p = 0; p < 8; p++) { \
            int row = p * 8 + w; \
            int j = _jb + row; \
            int kp = (j < SINKS_N) ? j : j + 1024; \
            const float* _ks; const float* _vs; \
            if (kp < PAST) { \
                size_t off = ((size_t)kvh * PAST + kp) * HD + d4c; \
                _ks = &g_pk[off]; _vs = &g_pv[off]; \
            } else { \
                size_t off = ((size_t)kvh * B_Q + (kp - PAST)) * HD + d4c; \
                _ks = &g_kt[off]; _vs = &g_vt[off]; \
            } \
            uint32_t doff = (uint32_t)(row * 132 + d4c) * 4; \
            CP16(_kb + doff, _ks); \
            CP16(_vb + doff, _vs); \
        } \
    } while (0)

    // prologue: tile 0 -> buffer 0
    CP_KV(0, 0);
    CP_COMMIT();

    for (int kt = 0; kt < ntiles; kt++) {
        const int jbase = kt * 64;
        const int buf = kt & 1;
        const bool pf = (kt + 1 < ntiles);

        CP_WAIT0();        // this thread's copies for `buf` done
        __syncthreads();   // all threads' copies visible; prior readers of buf^1 done

        if (pf) { CP_KV(kt + 1, buf ^ 1); CP_COMMIT(); }   // async prefetch

        // ---- S = Q @ K^T : 16 rows x 64 keys per warp ----
        float s[8][4];
#pragma unroll
        for (int nt = 0; nt < 8; nt++)
#pragma unroll
            for (int r = 0; r < 4; r++) s[nt][r] = 0.f;

#pragma unroll
        for (int ks = 0; ks < 16; ks++) {
#pragma unroll
            for (int ntp = 0; ntp < 4; ntp++) {
                unsigned bf[4];
                ldm_x4(bf, kmat[buf][ntp] + ks * 32);
                mma_tf32(s[2 * ntp],     qf[ks][0], qf[ks][1], qf[ks][2], qf[ks][3], bf[0], bf[1]);
                mma_tf32(s[2 * ntp + 1], qf[ks][0], qf[ks][1], qf[ks][2], qf[ks][3], bf[2], bf[3]);
            }
        }

        // ---- online softmax (base-2 domain, R9-verified) ----
#pragma unroll
        for (int half = 0; half < 2; half++) {
            const int rl  = rbase + g + half * 8;
            const int lim = 3072 + q0 + rl;
            float mx = -1e30f;
#pragma unroll
            for (int nt = 0; nt < 8; nt++)
#pragma unroll
                for (int rr = 0; rr < 2; rr++) {
                    int jg = jbase + nt * 8 + 2 * cq + rr;
                    float v = (jg <= lim) ? s[nt][half * 2 + rr] : -1e30f;
                    s[nt][half * 2 + rr] = v;
                    mx = fmaxf(mx, v);
                }
            mx = fmaxf(mx, __shfl_xor_sync(0xffffffffu, mx, 1));
            mx = fmaxf(mx, __shfl_xor_sync(0xffffffffu, mx, 2));
            float mnew = fmaxf(m_i[half], mx);
            float corr = exp2f(m_i[half] - mnew);
            m_i[half] = mnew;
            float rs = 0.f;
#pragma unroll
            for (int nt = 0; nt < 8; nt++) {
                float p0 = exp2f(s[nt][half * 2]     - mnew);
                float p1 = exp2f(s[nt][half * 2 + 1] - mnew);
                rs += p0 + p1;
                *(float2*)&Ps[rl][nt * 8 + 2 * cq] = make_float2(f2tff(p0), f2tff(p1));
            }
            rs += __shfl_xor_sync(0xffffffffu, rs, 1);
            rs += __shfl_xor_sync(0xffffffffu, rs, 2);
            l_i[half] = l_i[half] * corr + rs;
#pragma unroll
            for (int nt = 0; nt < 16; nt++) {
                o[nt][half * 2]     *= corr;
                o[nt][half * 2 + 1] *= corr;
            }
        }
        __syncwarp();   // Ps is warp-private

        // ---- O += P @ V : 16 rows x 128 d per warp, k-dim 64 (scalar V frags) ----
        const float* Vb = VsBuf[buf];
#pragma unroll
        for (int ks = 0; ks < 8; ks++) {
            const int k = ks * 8 + cq;
            unsigned a[4];
            ldm_x4(a, pmat + ks * 32);
#pragma unroll
            for (int nt = 0; nt < 16; nt++) {
                unsigned b0 = __float_as_uint(Vb[k * 132 + nt * 8 + g]);
                unsigned b1 = __float_as_uint(Vb[(k + 4) * 132 + nt * 8 + g]);
                mma_tf32(o[nt], a[0], a[1], a[2], a[3], b0, b1);
            }
        }
    }

    // ---- epilogue ----
    float inv0 = 1.0f / l_i[0];
    float inv1 = 1.0f / l_i[1];
    int row0 = q0 + rbase + g;
#pragma unroll
    for (int nt = 0; nt < 16; nt++) {
        int dd = nt * 8 + 2 * cq;
        *(float2*)&g_attn[(size_t)row0 * (NH * HD) + h * HD + dd] =
            make_float2(o[nt][0] * inv0, o[nt][1] * inv0);
        *(float2*)&g_attn[(size_t)(row0 + 8) * (NH * HD) + h * HD + dd] =
            make_float2(o[nt][2] * inv1, o[nt][3] * inv1);
    }
}

// ---------------- launch ----------------
extern "C" void kernel_launch(void* const* d_in, const int* in_sizes, int n_in,
                              void* d_out, int out_size)
{
    (void)in_sizes; (void)n_in; (void)out_size;
    const float* hidden = (const float*)d_in[0];
    const float* Wq     = (const float*)d_in[1];
    const float* Wk     = (const float*)d_in[2];
    const float* Wv     = (const float*)d_in[3];
    const float* Wo     = (const float*)d_in[4];
    const float* past_k = (const float*)d_in[5];
    const float* past_v = (const float*)d_in[6];
    const float* cosT   = (const float*)d_in[7];
    const float* sinT   = (const float*)d_in[8];

    void *p_attn;
    cudaGetSymbolAddress(&p_attn, g_attn);

    const int gemm_smem = (2 * 128 * 36 + 2 * 32 * 132) * 4;   // 70656 B
    cudaFuncSetAttribute(qkv_gemm, cudaFuncAttributeMaxDynamicSharedMemorySize, gemm_smem);
    cudaFuncSetAttribute(out_gemm, cudaFuncAttributeMaxDynamicSharedMemorySize, gemm_smem);
    const int attn_smem = (4 * 64 * 132 + 128 * 68) * 4;       // 169984 B
    cudaFuncSetAttribute(attn_tc, cudaFuncAttributeMaxDynamicSharedMemorySize, attn_smem);

    dim3 blk(256);
    preround_kernel<<<(NKV * PAST * HD) / 1024, 256>>>(past_k, past_v);
    qkv_gemm<<<dim3(48, 8), blk, gemm_smem>>>(hidden, Wq, Wk, Wv);
    rope_kernel<<<dim3(B_Q, 2 * NKV), 128>>>(cosT, sinT);
    attn_tc<<<dim3(NH, B_Q / 128), blk, attn_smem>>>(cosT, sinT);
    out_gemm<<<dim3(32, 8), blk, gemm_smem>>>((const float*)p_attn, Wo, (float*)d_out);
}

// round 14
// speedup vs baseline: 1.9475x; 1.2801x over previous
#include <cuda_runtime.h>
#include <cuda_fp16.h>
#include <cstdint>
#include <math.h>

// ---------------- problem constants ----------------
#define B_Q     1024
#define DM      4096
#define NH      32
#define NKV     8
#define HD      128
#define PAST    4096
#define SINKS_N 4
#define QSCALE   0.12751878662109375f   // fl(1/sqrt(128) * log2(e))

// ---------------- scratch ----------------
__device__ float  g_qbuf[B_Q * NH * HD];
__device__ float  g_kbuf[B_Q * NKV * HD];
__device__ float  g_vbuf[B_Q * NKV * HD];
__device__ __half g_kt[NKV * B_Q * HD];    // fp16 (rope)
__device__ __half g_vt[NKV * B_Q * HD];    // fp16 (rope)
__device__ __half g_pk[NKV * PAST * HD];   // fp16 past_k
__device__ __half g_pv[NKV * PAST * HD];   // fp16 past_v
__device__ float  g_attn[B_Q * NH * HD];

// ---------------- helpers ----------------
__device__ __forceinline__ uint32_t smem_u32(const void* p) {
    uint32_t a;
    asm("{ .reg .u64 t; cvta.to.shared.u64 t, %1; cvt.u32.u64 %0, t; }" : "=r"(a) : "l"(p));
    return a;
}
__device__ __forceinline__ unsigned f2tf(float x) {
    unsigned u; asm("cvt.rna.tf32.f32 %0, %1;" : "=r"(u) : "f"(x)); return u;
}
__device__ __forceinline__ float f2tff(float x) { return __uint_as_float(f2tf(x)); }

__device__ __forceinline__ void mma_tf32(float d[4],
    unsigned a0, unsigned a1, unsigned a2, unsigned a3, unsigned b0, unsigned b1)
{
    asm volatile(
        "mma.sync.aligned.m16n8k8.row.col.f32.tf32.tf32.f32 "
        "{%0,%1,%2,%3},{%4,%5,%6,%7},{%8,%9},{%0,%1,%2,%3};"
        : "+f"(d[0]), "+f"(d[1]), "+f"(d[2]), "+f"(d[3])
        : "r"(a0), "r"(a1), "r"(a2), "r"(a3), "r"(b0), "r"(b1));
}
__device__ __forceinline__ void mma_f16(float d[4],
    unsigned a0, unsigned a1, unsigned a2, unsigned a3, unsigned b0, unsigned b1)
{
    asm volatile(
        "mma.sync.aligned.m16n8k16.row.col.f32.f16.f16.f32 "
        "{%0,%1,%2,%3},{%4,%5,%6,%7},{%8,%9},{%0,%1,%2,%3};"
        : "+f"(d[0]), "+f"(d[1]), "+f"(d[2]), "+f"(d[3])
        : "r"(a0), "r"(a1), "r"(a2), "r"(a3), "r"(b0), "r"(b1));
}
__device__ __forceinline__ void ldm_x4(unsigned a[4], uint32_t addr) {
    asm volatile("ldmatrix.sync.aligned.m8n8.x4.shared.b16 {%0,%1,%2,%3}, [%4];"
        : "=r"(a[0]), "=r"(a[1]), "=r"(a[2]), "=r"(a[3]) : "r"(addr));
}
__device__ __forceinline__ void ldm_x4t(unsigned a[4], uint32_t addr) {
    asm volatile("ldmatrix.sync.aligned.m8n8.x4.trans.shared.b16 {%0,%1,%2,%3}, [%4];"
        : "=r"(a[0]), "=r"(a[1]), "=r"(a[2]), "=r"(a[3]) : "r"(addr));
}
__device__ __forceinline__ unsigned pack_h2(float lo, float hi) {
    __half2 h = __floats2half2_rn(lo, hi);
    return *(unsigned*)&h;
}
#define CP16(dst, src) \
    asm volatile("cp.async.cg.shared.global [%0], [%1], 16;" :: "r"(dst), "l"(src) : "memory")
#define CP_COMMIT() asm volatile("cp.async.commit_group;" ::: "memory")
#define CP_WAIT0()  asm volatile("cp.async.wait_group 0;" ::: "memory")

// ---------------- GEMM core (verified R5/R7 version, frozen) ----------------
__device__ __forceinline__ void gemm_core(
    const float* __restrict__ A, const float* __restrict__ B,
    float* __restrict__ C, int N, int K, int m0, int n0, float* smg)
{
    float* As[2] = { smg, smg + 128 * 36 };
    float* Bs[2] = { smg + 2 * 128 * 36, smg + 2 * 128 * 36 + 32 * 132 };

    const int tid  = threadIdx.x;
    const int w    = tid >> 5, lane = tid & 31;
    const int g    = lane >> 2, cq = lane & 3;
    const int wm   = w & 1, wn = w >> 1;

    const int ar  = tid >> 3, ac4 = (tid & 7) * 4;
    const int bkr = tid >> 5, bn4 = (tid & 31) * 4;

    const int lrow = ((lane >> 3) & 1) * 8 + (lane & 7);
    const int lcol = (lane >> 4) * 4;
    int aoff[4];
#pragma unroll
    for (int mt = 0; mt < 4; mt++)
        aoff[mt] = ((wm * 64 + mt * 16 + lrow) * 36 + lcol) * 4;
    const uint32_t as_u[2] = { smem_u32(As[0]), smem_u32(As[1]) };

    float acc[4][4][4];
#pragma unroll
    for (int i = 0; i < 4; i++)
#pragma unroll
        for (int j = 0; j < 4; j++)
#pragma unroll
            for (int r = 0; r < 4; r++) acc[i][j][r] = 0.f;

    const int ns = K >> 5;
    float4 ra[4], rb[4];
#pragma unroll
    for (int p = 0; p < 4; p++) {
        ra[p] = *(const float4*)&A[(size_t)(m0 + ar + p * 32) * K + ac4];
        rb[p] = *(const float4*)&B[(size_t)(bkr + p * 8) * N + n0 + bn4];
    }

    for (int i = 0; i < ns; i++) {
        float* Ab = As[i & 1];
        float* Bb = Bs[i & 1];
        const uint32_t abu = as_u[i & 1];
#pragma unroll
        for (int p = 0; p < 4; p++) {
            *(float4*)&Ab[(ar + p * 32) * 36 + ac4] =
                make_float4(f2tff(ra[p].x), f2tff(ra[p].y), f2tff(ra[p].z), f2tff(ra[p].w));
            *(float4*)&Bb[(bkr + p * 8) * 132 + bn4] =
                make_float4(f2tff(rb[p].x), f2tff(rb[p].y), f2tff(rb[p].z), f2tff(rb[p].w));
        }
        __syncthreads();

        if (i + 1 < ns) {
            const int k0 = (i + 1) * 32;
#pragma unroll
            for (int p = 0; p < 4; p++) {
                ra[p] = *(const float4*)&A[(size_t)(m0 + ar + p * 32) * K + k0 + ac4];
                rb[p] = *(const float4*)&B[(size_t)(k0 + bkr + p * 8) * N + n0 + bn4];
            }
        }

#pragma unroll
        for (int ks = 0; ks < 4; ks++) {
            const int k = ks * 8 + cq;
            unsigned a[4][4], b[4][2];
#pragma unroll
            for (int mt = 0; mt < 4; mt++)
                ldm_x4(a[mt], abu + aoff[mt] + ks * 32);
#pragma unroll
            for (int nt = 0; nt < 4; nt++) {
                int n = wn * 32 + nt * 8 + g;
                b[nt][0] = __float_as_uint(Bb[k * 132 + n]);
                b[nt][1] = __float_as_uint(Bb[(k + 4) * 132 + n]);
            }
#pragma unroll
            for (int mt = 0; mt < 4; mt++)
#pragma unroll
                for (int nt = 0; nt < 4; nt++)
                    mma_tf32(acc[mt][nt], a[mt][0], a[mt][1], a[mt][2], a[mt][3],
                             b[nt][0], b[nt][1]);
        }
    }

#pragma unroll
    for (int mt = 0; mt < 4; mt++)
#pragma unroll
        for (int nt = 0; nt < 4; nt++) {
            int r  = m0 + wm * 64 + mt * 16 + g;
            int cc = n0 + wn * 32 + nt * 8 + 2 * cq;
            *(float2*)&C[(size_t)r * N + cc]       = make_float2(acc[mt][nt][0], acc[mt][nt][1]);
            *(float2*)&C[(size_t)(r + 8) * N + cc] = make_float2(acc[mt][nt][2], acc[mt][nt][3]);
        }
}

__global__ __launch_bounds__(256, 2) void qkv_gemm(
    const float* __restrict__ hidden, const float* __restrict__ Wq,
    const float* __restrict__ Wk, const float* __restrict__ Wv)
{
    extern __shared__ float smg[];
    const int bx = blockIdx.x;
    const float* B; float* C; int N, n0;
    if (bx < 32)      { B = Wq; C = g_qbuf; N = NH * HD;  n0 = bx * 128; }
    else if (bx < 40) { B = Wk; C = g_kbuf; N = NKV * HD; n0 = (bx - 32) * 128; }
    else              { B = Wv; C = g_vbuf; N = NKV * HD; n0 = (bx - 40) * 128; }
    gemm_core(hidden, B, C, N, DM, blockIdx.y * 128, n0, smg);
}

__global__ __launch_bounds__(256, 2) void out_gemm(
    const float* __restrict__ A, const float* __restrict__ Wo, float* __restrict__ C)
{
    extern __shared__ float smg[];
    gemm_core(A, Wo, C, DM, NH * HD, blockIdx.y * 128, blockIdx.x * 128, smg);
}

// ---------------- pre-convert past K/V to fp16 ----------------
__global__ void preround_kernel(const float* __restrict__ pk, const float* __restrict__ pv)
{
    size_t i = ((size_t)blockIdx.x * 256 + threadIdx.x) * 4;
    float4 a = *(const float4*)&pk[i];
    float4 b = *(const float4*)&pv[i];
    uint2 ha = make_uint2(pack_h2(a.x, a.y), pack_h2(a.z, a.w));
    uint2 hb = make_uint2(pack_h2(b.x, b.y), pack_h2(b.z, b.w));
    *(uint2*)&g_pk[i] = ha;
    *(uint2*)&g_pv[i] = hb;
}

// ---------------- RoPE + transpose (K/V only), fp16 outputs ----------------
__global__ void rope_kernel(const float* __restrict__ cosT, const float* __restrict__ sinT)
{
    const int qi   = blockIdx.x;
    const int slot = blockIdx.y;
    const int d    = threadIdx.x;
    const int pos  = PAST + qi;

    if (slot < NKV) {
        const int h = slot;
        const float c = cosT[pos * HD + d];
        const float s = sinT[pos * HD + d];
        const float* src = g_kbuf + (size_t)qi * (NKV * HD) + h * HD;
        float x = src[d], y = src[d ^ 64];
        g_kt[((size_t)h * B_Q + qi) * HD + d] = __float2half_rn(x * c + ((d < 64) ? -y : y) * s);
    } else {
        const int h = slot - NKV;
        g_vt[((size_t)h * B_Q + qi) * HD + d] =
            __float2half_rn(g_vbuf[(size_t)qi * (NKV * HD) + h * HD + d]);
    }
}

// ---------------- Flash attention: fp16 mma + cp.async double buffering ----------------
// 256 threads = 8 warps. Q-tile 128 (warp w: rows w*16..+15), K-tile 64.
// fp16 operands everywhere (11-bit mantissa = tf32-class accuracy), fp32 accum.
// Smem (halves): Ks0[64x136] Ks1 Vs0[64x136] Vs1 Ps[128x72]; Q staged over Ks region.
// LPT grid: blockIdx.x = head, qtile = 7 - blockIdx.y.
__global__ __launch_bounds__(256) void attn_tc(
    const float* __restrict__ cosT, const float* __restrict__ sinT)
{
    extern __shared__ __half smh[];
    __half* Ks[2] = { smh,          smh + 8704 };
    __half* Vs[2] = { smh + 17408,  smh + 26112 };
    __half* Ps    = smh + 34816;                    // 128 x 72

    const int tid = threadIdx.x;
    const int w = tid >> 5, lane = tid & 31;
    const int g = lane >> 2, cq = lane & 3;
    const int h  = blockIdx.x;
    const int q0 = (7 - blockIdx.y) * 128;
    const int kvh = h >> 2;
    const int rbase = w * 16;

    // ---- stage Q (fp16, stride 136) with fused RoPE + QSCALE over Ks region ----
#pragma unroll
    for (int p = 0; p < 8; p++) {
        int e = p * 256 + tid;
        int row = e >> 4, c8 = (e & 15) * 8;
        const float* src = &g_qbuf[(size_t)(q0 + row) * (NH * HD) + h * HD];
        const int pos = PAST + q0 + row;
        float sgn = (c8 < 64) ? -1.f : 1.f;
        unsigned out[4];
#pragma unroll
        for (int q4 = 0; q4 < 2; q4++) {
            int d4 = c8 + q4 * 4;
            float4 x = *(const float4*)&src[d4];
            float4 y = *(const float4*)&src[d4 ^ 64];
            float4 c = *(const float4*)&cosT[pos * HD + d4];
            float4 s = *(const float4*)&sinT[pos * HD + d4];
            float r0 = (x.x * c.x + sgn * y.x * s.x) * QSCALE;
            float r1 = (x.y * c.y + sgn * y.y * s.y) * QSCALE;
            float r2 = (x.z * c.z + sgn * y.z * s.z) * QSCALE;
            float r3 = (x.w * c.w + sgn * y.w * s.w) * QSCALE;
            out[q4 * 2]     = pack_h2(r0, r1);
            out[q4 * 2 + 1] = pack_h2(r2, r3);
        }
        *(uint4*)&smh[row * 136 + c8] = make_uint4(out[0], out[1], out[2], out[3]);
    }
    __syncthreads();

    // ---- Q A-frags -> registers (8 k16-chunks x 4 regs) ----
    const int lrow = rbase + ((lane >> 3) & 1) * 8 + (lane & 7);
    const uint32_t qmat = smem_u32(smh) + (lrow * 136 + (lane >> 4) * 8) * 2;
    unsigned qf[8][4];
#pragma unroll
    for (int kc = 0; kc < 8; kc++)
        ldm_x4(qf[kc], qmat + kc * 32);
    __syncthreads();   // Q staging reads done before cp.async overwrites Ks

    const uint32_t ps_u = smem_u32(Ps);
    const uint32_t pmat = ps_u + (lrow * 72 + (lane >> 4) * 8) * 2;
    const uint32_t ks_u[2] = { smem_u32(Ks[0]), smem_u32(Ks[1]) };
    const uint32_t vs_u[2] = { smem_u32(Vs[0]), smem_u32(Vs[1]) };

    // S-loop B-frag bases (Ks non-trans): rows=keys, cols=d
    const int l7 = lane & 7;
    uint32_t kmat[2][4], vmat[2][8];
#pragma unroll
    for (int b = 0; b < 2; b++) {
#pragma unroll
        for (int ntp = 0; ntp < 4; ntp++) {
            int row = ntp * 16 + ((lane >> 4) & 1) * 8 + l7;
            kmat[b][ntp] = ks_u[b] + (row * 136 + ((lane >> 3) & 1) * 8) * 2;
        }
        // PV B-frag bases (Vs trans): rows=keys(kc), cols=d(ntp)
#pragma unroll
        for (int ntp = 0; ntp < 8; ntp++) {
            int krow = ((lane >> 3) & 1) * 8 + l7;
            int dcol = ntp * 16 + ((lane >> 4) & 1) * 8;
            vmat[b][ntp] = vs_u[b] + (krow * 136 + dcol) * 2;
        }
    }

    float m_i[2], l_i[2];
    float o[16][4];
    m_i[0] = m_i[1] = -1e30f;
    l_i[0] = l_i[1] = 0.f;
#pragma unroll
    for (int nt = 0; nt < 16; nt++)
#pragma unroll
        for (int r = 0; r < 4; r++) o[nt][r] = 0.f;

    const int ntiles = ((3072 + q0 + 127) >> 6) + 1;

    // cp.async: 4 chunks each for K and V per thread per tile (16B = 8 halves)
#define CP_KV(KT, BUF) do { \
        const int _jb = (KT) * 64; \
        const uint32_t _kb = ks_u[BUF], _vb = vs_u[BUF]; \
        _Pragma("unroll") \
        for (int p = 0; p < 4; p++) { \
            int c = p * 256 + tid; \
            int row = c >> 4, ch = c & 15; \
            int j = _jb + row; \
            int kp = (j < SINKS_N) ? j : j + 1024; \
            const __half* _ks; const __half* _vs; \
            if (kp < PAST) { \
                size_t off = ((size_t)kvh * PAST + kp) * HD + ch * 8; \
                _ks = &g_pk[off]; _vs = &g_pv[off]; \
            } else { \
                size_t off = ((size_t)kvh * B_Q + (kp - PAST)) * HD + ch * 8; \
                _ks = &g_kt[off]; _vs = &g_vt[off]; \
            } \
            uint32_t doff = (uint32_t)(row * 136 + ch * 8) * 2; \
            CP16(_kb + doff, _ks); \
            CP16(_vb + doff, _vs); \
        } \
    } while (0)

    CP_KV(0, 0);
    CP_COMMIT();

    for (int kt = 0; kt < ntiles; kt++) {
        const int jbase = kt * 64;
        const int buf = kt & 1;
        const bool pf = (kt + 1 < ntiles);

        CP_WAIT0();
        __syncthreads();

        if (pf) { CP_KV(kt + 1, buf ^ 1); CP_COMMIT(); }

        // ---- S = Q @ K^T : 16 rows x 64 keys per warp, k16 mma ----
        float s[8][4];
#pragma unroll
        for (int nt = 0; nt < 8; nt++)
#pragma unroll
            for (int r = 0; r < 4; r++) s[nt][r] = 0.f;

#pragma unroll
        for (int kc = 0; kc < 8; kc++) {
#pragma unroll
            for (int ntp = 0; ntp < 4; ntp++) {
                unsigned bf[4];
                ldm_x4(bf, kmat[buf][ntp] + kc * 32);
                mma_f16(s[2 * ntp],     qf[kc][0], qf[kc][1], qf[kc][2], qf[kc][3], bf[0], bf[1]);
                mma_f16(s[2 * ntp + 1], qf[kc][0], qf[kc][1], qf[kc][2], qf[kc][3], bf[2], bf[3]);
            }
        }

        // ---- online softmax (base-2 domain, R9-verified) ----
#pragma unroll
        for (int half = 0; half < 2; half++) {
            const int rl  = rbase + g + half * 8;
            const int lim = 3072 + q0 + rl;
            float mx = -1e30f;
#pragma unroll
            for (int nt = 0; nt < 8; nt++)
#pragma unroll
                for (int rr = 0; rr < 2; rr++) {
                    int jg = jbase + nt * 8 + 2 * cq + rr;
                    float v = (jg <= lim) ? s[nt][half * 2 + rr] : -1e30f;
                    s[nt][half * 2 + rr] = v;
                    mx = fmaxf(mx, v);
                }
            mx = fmaxf(mx, __shfl_xor_sync(0xffffffffu, mx, 1));
            mx = fmaxf(mx, __shfl_xor_sync(0xffffffffu, mx, 2));
            float mnew = fmaxf(m_i[half], mx);
            float corr = exp2f(m_i[half] - mnew);
            m_i[half] = mnew;
            float rs = 0.f;
#pragma unroll
            for (int nt = 0; nt < 8; nt++) {
                float p0 = exp2f(s[nt][half * 2]     - mnew);
                float p1 = exp2f(s[nt][half * 2 + 1] - mnew);
                rs += p0 + p1;
                *(unsigned*)&Ps[rl * 72 + nt * 8 + 2 * cq] = pack_h2(p0, p1);
            }
            rs += __shfl_xor_sync(0xffffffffu, rs, 1);
            rs += __shfl_xor_sync(0xffffffffu, rs, 2);
            l_i[half] = l_i[half] * corr + rs;
#pragma unroll
            for (int nt = 0; nt < 16; nt++) {
                o[nt][half * 2]     *= corr;
                o[nt][half * 2 + 1] *= corr;
            }
        }
        __syncwarp();   // Ps is warp-private

        // ---- O += P @ V : 16 rows x 128 d per warp, 4 k16-chunks ----
#pragma unroll
        for (int kc = 0; kc < 4; kc++) {
            unsigned a[4];
            ldm_x4(a, pmat + kc * 32);
            const uint32_t koff = (uint32_t)kc * (16 * 136 * 2);
#pragma unroll
            for (int ntp = 0; ntp < 8; ntp++) {
                unsigned bf[4];
                ldm_x4t(bf, vmat[buf][ntp] + koff);
                mma_f16(o[2 * ntp],     a[0], a[1], a[2], a[3], bf[0], bf[1]);
                mma_f16(o[2 * ntp + 1], a[0], a[1], a[2], a[3], bf[2], bf[3]);
            }
        }
    }

    // ---- epilogue ----
    float inv0 = 1.0f / l_i[0];
    float inv1 = 1.0f / l_i[1];
    int row0 = q0 + rbase + g;
#pragma unroll
    for (int nt = 0; nt < 16; nt++) {
        int dd = nt * 8 + 2 * cq;
        *(float2*)&g_attn[(size_t)row0 * (NH * HD) + h * HD + dd] =
            make_float2(o[nt][0] * inv0, o[nt][1] * inv0);
        *(float2*)&g_attn[(size_t)(row0 + 8) * (NH * HD) + h * HD + dd] =
            make_float2(o[nt][2] * inv1, o[nt][3] * inv1);
    }
}

// ---------------- launch ----------------
extern "C" void kernel_launch(void* const* d_in, const int* in_sizes, int n_in,
                              void* d_out, int out_size)
{
    (void)in_sizes; (void)n_in; (void)out_size;
    const float* hidden = (const float*)d_in[0];
    const float* Wq     = (const float*)d_in[1];
    const float* Wk     = (const float*)d_in[2];
    const float* Wv     = (const float*)d_in[3];
    const float* Wo     = (const float*)d_in[4];
    const float* past_k = (const float*)d_in[5];
    const float* past_v = (const float*)d_in[6];
    const float* cosT   = (const float*)d_in[7];
    const float* sinT   = (const float*)d_in[8];

    void *p_attn;
    cudaGetSymbolAddress(&p_attn, g_attn);

    const int gemm_smem = (2 * 128 * 36 + 2 * 32 * 132) * 4;   // 70656 B
    cudaFuncSetAttribute(qkv_gemm, cudaFuncAttributeMaxDynamicSharedMemorySize, gemm_smem);
    cudaFuncSetAttribute(out_gemm, cudaFuncAttributeMaxDynamicSharedMemorySize, gemm_smem);
    const int attn_smem = (34816 + 128 * 72) * 2;              // 88064 B
    cudaFuncSetAttribute(attn_tc, cudaFuncAttributeMaxDynamicSharedMemorySize, attn_smem);

    dim3 blk(256);
    preround_kernel<<<(NKV * PAST * HD) / 1024, 256>>>(past_k, past_v);
    qkv_gemm<<<dim3(48, 8), blk, gemm_smem>>>(hidden, Wq, Wk, Wv);
    rope_kernel<<<dim3(B_Q, 2 * NKV), 128>>>(cosT, sinT);
    attn_tc<<<dim3(NH, B_Q / 128), blk, attn_smem>>>(cosT, sinT);
    out_gemm<<<dim3(32, 8), blk, gemm_smem>>>((const float*)p_attn, Wo, (float*)d_out);
}

// round 15
// speedup vs baseline: 3.1623x; 1.6237x over previous
#include <cuda_runtime.h>
#include <cuda_fp16.h>
#include <cstdint>
#include <math.h>

// ---------------- problem constants ----------------
#define B_Q     1024
#define DM      4096
#define NH      32
#define NKV     8
#define HD      128
#define PAST    4096
#define SINKS_N 4
#define QSCALE   0.12751878662109375f   // fl(1/sqrt(128) * log2(e))

// ---------------- scratch ----------------
__device__ float  g_qbuf[B_Q * NH * HD];
__device__ float  g_kbuf[B_Q * NKV * HD];
__device__ float  g_vbuf[B_Q * NKV * HD];
__device__ __half g_kt[NKV * B_Q * HD];
__device__ __half g_vt[NKV * B_Q * HD];
__device__ __half g_pk[NKV * PAST * HD];
__device__ __half g_pv[NKV * PAST * HD];
__device__ __half h_attn[B_Q * NH * HD];      // fp16 attention output (A of out_gemm)
__device__ __half h_hidden[B_Q * DM];
__device__ __half h_Wq[DM * NH * HD];
__device__ __half h_Wk[DM * NKV * HD];
__device__ __half h_Wv[DM * NKV * HD];
__device__ __half h_Wo[NH * HD * DM];

// ---------------- helpers ----------------
__device__ __forceinline__ uint32_t smem_u32(const void* p) {
    uint32_t a;
    asm("{ .reg .u64 t; cvta.to.shared.u64 t, %1; cvt.u32.u64 %0, t; }" : "=r"(a) : "l"(p));
    return a;
}
__device__ __forceinline__ void mma_f16(float d[4],
    unsigned a0, unsigned a1, unsigned a2, unsigned a3, unsigned b0, unsigned b1)
{
    asm volatile(
        "mma.sync.aligned.m16n8k16.row.col.f32.f16.f16.f32 "
        "{%0,%1,%2,%3},{%4,%5,%6,%7},{%8,%9},{%0,%1,%2,%3};"
        : "+f"(d[0]), "+f"(d[1]), "+f"(d[2]), "+f"(d[3])
        : "r"(a0), "r"(a1), "r"(a2), "r"(a3), "r"(b0), "r"(b1));
}
__device__ __forceinline__ void ldm_x4(unsigned a[4], uint32_t addr) {
    asm volatile("ldmatrix.sync.aligned.m8n8.x4.shared.b16 {%0,%1,%2,%3}, [%4];"
        : "=r"(a[0]), "=r"(a[1]), "=r"(a[2]), "=r"(a[3]) : "r"(addr));
}
__device__ __forceinline__ void ldm_x4t(unsigned a[4], uint32_t addr) {
    asm volatile("ldmatrix.sync.aligned.m8n8.x4.trans.shared.b16 {%0,%1,%2,%3}, [%4];"
        : "=r"(a[0]), "=r"(a[1]), "=r"(a[2]), "=r"(a[3]) : "r"(addr));
}
__device__ __forceinline__ unsigned pack_h2(float lo, float hi) {
    __half2 h = __floats2half2_rn(lo, hi);
    return *(unsigned*)&h;
}
#define CP16(dst, src) \
    asm volatile("cp.async.cg.shared.global [%0], [%1], 16;" :: "r"(dst), "l"(src) : "memory")
#define CP_COMMIT() asm volatile("cp.async.commit_group;" ::: "memory")
#define CP_WAIT0()  asm volatile("cp.async.wait_group 0;" ::: "memory")

// ---------------- generic fp32 -> fp16 convert ----------------
__global__ void cvt_kernel(const float* __restrict__ src, __half* __restrict__ dst)
{
    size_t i = ((size_t)blockIdx.x * 256 + threadIdx.x) * 4;
    float4 a = *(const float4*)&src[i];
    *(uint2*)&dst[i] = make_uint2(pack_h2(a.x, a.y), pack_h2(a.z, a.w));
}

// ---------------- fp16 GEMM core: C[.,N] = A[.,K] @ B[K,N] ----------------
// A fp16 [M][K] row-major, B fp16 [K][N] row-major, C fp32.
// Block 128x128, k-stage 32, 8 warps (2x4), warp tile 64x32.
// cp.async double-buffered; A-frags ldm_x4 (stride-40 rows, conflict-free);
// B-frags ldm_x4t on natural [k][n] tile (R14-verified V pattern).
__device__ __forceinline__ void gemm16(
    const __half* __restrict__ A, const __half* __restrict__ B,
    float* __restrict__ C, int N, int K, int m0, int n0, __half* smh)
{
    // halves offsets: As0=0, As1=5120, Bs0=10240, Bs1=14592 (total 18944 h = 37888 B)
    const uint32_t sb = smem_u32(smh);
    const uint32_t as_u[2] = { sb,           sb + 5120 * 2 };
    const uint32_t bs_u[2] = { sb + 10240 * 2, sb + 14592 * 2 };

    const int tid  = threadIdx.x;
    const int w    = tid >> 5, lane = tid & 31;
    const int g    = lane >> 2, cq = lane & 3;
    const int wm   = w & 1, wn = w >> 1;
    const int l7   = lane & 7;

    // A-frag bases: rows wm*64+mt*16+..., col chunk (lane>>4)*8 halves
    const int lrow = ((lane >> 3) & 1) * 8 + l7;
    uint32_t aoff[4];
#pragma unroll
    for (int mt = 0; mt < 4; mt++)
        aoff[mt] = (uint32_t)((wm * 64 + mt * 16 + lrow) * 40 + (lane >> 4) * 8) * 2;

    // B-frag bases (trans): krow 0..15 within stage, dcol = wn*32 + ntp*16 + ...
    const int bkrow = ((lane >> 3) & 1) * 8 + l7;
    uint32_t boff[2];
#pragma unroll
    for (int ntp = 0; ntp < 2; ntp++)
        boff[ntp] = (uint32_t)(bkrow * 136 + wn * 32 + ntp * 16 + ((lane >> 4) & 1) * 8) * 2;

    float acc[4][4][4];
#pragma unroll
    for (int i = 0; i < 4; i++)
#pragma unroll
        for (int j = 0; j < 4; j++)
#pragma unroll
            for (int r = 0; r < 4; r++) acc[i][j][r] = 0.f;

    const int ns = K >> 5;

    // cp.async one stage: A 512 chunks (128 rows x 4), B 512 chunks (32 rows x 16)
#define GEMM_CP(I, BUF) do { \
        const int _k0 = (I) * 32; \
        const uint32_t _ab = as_u[BUF], _bb = bs_u[BUF]; \
        _Pragma("unroll") \
        for (int p = 0; p < 2; p++) { \
            int c = p * 256 + tid; \
            int row = c >> 2, col = (c & 3) * 8; \
            CP16(_ab + (uint32_t)(row * 40 + col) * 2, \
                 &A[(size_t)(m0 + row) * K + _k0 + col]); \
        } \
        _Pragma("unroll") \
        for (int p = 0; p < 2; p++) { \
            int c = p * 256 + tid; \
            int row = c >> 4, col = (c & 15) * 8; \
            CP16(_bb + (uint32_t)(row * 136 + col) * 2, \
                 &B[(size_t)(_k0 + row) * N + n0 + col]); \
        } \
    } while (0)

    GEMM_CP(0, 0);
    CP_COMMIT();

    for (int i = 0; i < ns; i++) {
        const int buf = i & 1;
        CP_WAIT0();
        __syncthreads();

        if (i + 1 < ns) { GEMM_CP(i + 1, buf ^ 1); CP_COMMIT(); }

#pragma unroll
        for (int kc = 0; kc < 2; kc++) {
            unsigned a[4][4];
#pragma unroll
            for (int mt = 0; mt < 4; mt++)
                ldm_x4(a[mt], as_u[buf] + aoff[mt] + kc * 32);
#pragma unroll
            for (int ntp = 0; ntp < 2; ntp++) {
                unsigned bf[4];
                ldm_x4t(bf, bs_u[buf] + boff[ntp] + (uint32_t)kc * (16 * 136 * 2));
#pragma unroll
                for (int mt = 0; mt < 4; mt++) {
                    mma_f16(acc[mt][2 * ntp],     a[mt][0], a[mt][1], a[mt][2], a[mt][3], bf[0], bf[1]);
                    mma_f16(acc[mt][2 * ntp + 1], a[mt][0], a[mt][1], a[mt][2], a[mt][3], bf[2], bf[3]);
                }
            }
        }
        __syncthreads();   // all frag reads done before next stage overwrites buf
    }

#pragma unroll
    for (int mt = 0; mt < 4; mt++)
#pragma unroll
        for (int nt = 0; nt < 4; nt++) {
            int r  = m0 + wm * 64 + mt * 16 + g;
            int cc = n0 + wn * 32 + nt * 8 + 2 * cq;
            *(float2*)&C[(size_t)r * N + cc]       = make_float2(acc[mt][nt][0], acc[mt][nt][1]);
            *(float2*)&C[(size_t)(r + 8) * N + cc] = make_float2(acc[mt][nt][2], acc[mt][nt][3]);
        }
}

__global__ __launch_bounds__(256, 2) void qkv_gemm()
{
    extern __shared__ __half smh[];
    const int bx = blockIdx.x;
    const __half* B; float* C; int N, n0;
    if (bx < 32)      { B = h_Wq; C = g_qbuf; N = NH * HD;  n0 = bx * 128; }
    else if (bx < 40) { B = h_Wk; C = g_kbuf; N = NKV * HD; n0 = (bx - 32) * 128; }
    else              { B = h_Wv; C = g_vbuf; N = NKV * HD; n0 = (bx - 40) * 128; }
    gemm16(h_hidden, B, C, N, DM, blockIdx.y * 128, n0, smh);
}

__global__ __launch_bounds__(256, 2) void out_gemm(float* __restrict__ out)
{
    extern __shared__ __half smh[];
    gemm16(h_attn, h_Wo, out, DM, NH * HD, blockIdx.y * 128, blockIdx.x * 128, smh);
}

// ---------------- RoPE + transpose (K/V only), fp16 outputs ----------------
__global__ void rope_kernel(const float* __restrict__ cosT, const float* __restrict__ sinT)
{
    const int qi   = blockIdx.x;
    const int slot = blockIdx.y;
    const int d    = threadIdx.x;
    const int pos  = PAST + qi;

    if (slot < NKV) {
        const int h = slot;
        const float c = cosT[pos * HD + d];
        const float s = sinT[pos * HD + d];
        const float* src = g_kbuf + (size_t)qi * (NKV * HD) + h * HD;
        float x = src[d], y = src[d ^ 64];
        g_kt[((size_t)h * B_Q + qi) * HD + d] = __float2half_rn(x * c + ((d < 64) ? -y : y) * s);
    } else {
        const int h = slot - NKV;
        g_vt[((size_t)h * B_Q + qi) * HD + d] =
            __float2half_rn(g_vbuf[(size_t)qi * (NKV * HD) + h * HD + d]);
    }
}

// ---------------- Flash attention (R14-verified) + fp16 epilogue ----------------
__global__ __launch_bounds__(256) void attn_tc(
    const float* __restrict__ cosT, const float* __restrict__ sinT)
{
    extern __shared__ __half smh[];
    __half* Ks[2] = { smh,          smh + 8704 };
    __half* Vs[2] = { smh + 17408,  smh + 26112 };
    __half* Ps    = smh + 34816;                    // 128 x 72

    const int tid = threadIdx.x;
    const int w = tid >> 5, lane = tid & 31;
    const int g = lane >> 2, cq = lane & 3;
    const int h  = blockIdx.x;
    const int q0 = (7 - blockIdx.y) * 128;
    const int kvh = h >> 2;
    const int rbase = w * 16;

    // ---- stage Q (fp16, stride 136) with fused RoPE + QSCALE over Ks region ----
#pragma unroll
    for (int p = 0; p < 8; p++) {
        int e = p * 256 + tid;
        int row = e >> 4, c8 = (e & 15) * 8;
        const float* src = &g_qbuf[(size_t)(q0 + row) * (NH * HD) + h * HD];
        const int pos = PAST + q0 + row;
        float sgn = (c8 < 64) ? -1.f : 1.f;
        unsigned out[4];
#pragma unroll
        for (int q4 = 0; q4 < 2; q4++) {
            int d4 = c8 + q4 * 4;
            float4 x = *(const float4*)&src[d4];
            float4 y = *(const float4*)&src[d4 ^ 64];
            float4 c = *(const float4*)&cosT[pos * HD + d4];
            float4 s = *(const float4*)&sinT[pos * HD + d4];
            float r0 = (x.x * c.x + sgn * y.x * s.x) * QSCALE;
            float r1 = (x.y * c.y + sgn * y.y * s.y) * QSCALE;
            float r2 = (x.z * c.z + sgn * y.z * s.z) * QSCALE;
            float r3 = (x.w * c.w + sgn * y.w * s.w) * QSCALE;
            out[q4 * 2]     = pack_h2(r0, r1);
            out[q4 * 2 + 1] = pack_h2(r2, r3);
        }
        *(uint4*)&smh[row * 136 + c8] = make_uint4(out[0], out[1], out[2], out[3]);
    }
    __syncthreads();

    const int lrow = rbase + ((lane >> 3) & 1) * 8 + (lane & 7);
    const uint32_t qmat = smem_u32(smh) + (lrow * 136 + (lane >> 4) * 8) * 2;
    unsigned qf[8][4];
#pragma unroll
    for (int kc = 0; kc < 8; kc++)
        ldm_x4(qf[kc], qmat + kc * 32);
    __syncthreads();

    const uint32_t ps_u = smem_u32(Ps);
    const uint32_t pmat = ps_u + (lrow * 72 + (lane >> 4) * 8) * 2;
    const uint32_t ks_u[2] = { smem_u32(Ks[0]), smem_u32(Ks[1]) };
    const uint32_t vs_u[2] = { smem_u32(Vs[0]), smem_u32(Vs[1]) };

    const int l7 = lane & 7;
    uint32_t kmat[2][4], vmat[2][8];
#pragma unroll
    for (int b = 0; b < 2; b++) {
#pragma unroll
        for (int ntp = 0; ntp < 4; ntp++) {
            int row = ntp * 16 + ((lane >> 4) & 1) * 8 + l7;
            kmat[b][ntp] = ks_u[b] + (row * 136 + ((lane >> 3) & 1) * 8) * 2;
        }
#pragma unroll
        for (int ntp = 0; ntp < 8; ntp++) {
            int krow = ((lane >> 3) & 1) * 8 + l7;
            int dcol = ntp * 16 + ((lane >> 4) & 1) * 8;
            vmat[b][ntp] = vs_u[b] + (krow * 136 + dcol) * 2;
        }
    }

    float m_i[2], l_i[2];
    float o[16][4];
    m_i[0] = m_i[1] = -1e30f;
    l_i[0] = l_i[1] = 0.f;
#pragma unroll
    for (int nt = 0; nt < 16; nt++)
#pragma unroll
        for (int r = 0; r < 4; r++) o[nt][r] = 0.f;

    const int ntiles = ((3072 + q0 + 127) >> 6) + 1;

#define CP_KV(KT, BUF) do { \
        const int _jb = (KT) * 64; \
        const uint32_t _kb = ks_u[BUF], _vb = vs_u[BUF]; \
        _Pragma("unroll") \
        for (int p = 0; p < 4; p++) { \
            int c = p * 256 + tid; \
            int row = c >> 4, ch = c & 15; \
            int j = _jb + row; \
            int kp = (j < SINKS_N) ? j : j + 1024; \
            const __half* _ks; const __half* _vs; \
            if (kp < PAST) { \
                size_t off = ((size_t)kvh * PAST + kp) * HD + ch * 8; \
                _ks = &g_pk[off]; _vs = &g_pv[off]; \
            } else { \
                size_t off = ((size_t)kvh * B_Q + (kp - PAST)) * HD + ch * 8; \
                _ks = &g_kt[off]; _vs = &g_vt[off]; \
            } \
            uint32_t doff = (uint32_t)(row * 136 + ch * 8) * 2; \
            CP16(_kb + doff, _ks); \
            CP16(_vb + doff, _vs); \
        } \
    } while (0)

    CP_KV(0, 0);
    CP_COMMIT();

    for (int kt = 0; kt < ntiles; kt++) {
        const int jbase = kt * 64;
        const int buf = kt & 1;
        const bool pf = (kt + 1 < ntiles);

        CP_WAIT0();
        __syncthreads();

        if (pf) { CP_KV(kt + 1, buf ^ 1); CP_COMMIT(); }

        float s[8][4];
#pragma unroll
        for (int nt = 0; nt < 8; nt++)
#pragma unroll
            for (int r = 0; r < 4; r++) s[nt][r] = 0.f;

#pragma unroll
        for (int kc = 0; kc < 8; kc++) {
#pragma unroll
            for (int ntp = 0; ntp < 4; ntp++) {
                unsigned bf[4];
                ldm_x4(bf, kmat[buf][ntp] + kc * 32);
                mma_f16(s[2 * ntp],     qf[kc][0], qf[kc][1], qf[kc][2], qf[kc][3], bf[0], bf[1]);
                mma_f16(s[2 * ntp + 1], qf[kc][0], qf[kc][1], qf[kc][2], qf[kc][3], bf[2], bf[3]);
            }
        }

#pragma unroll
        for (int half = 0; half < 2; half++) {
            const int rl  = rbase + g + half * 8;
            const int lim = 3072 + q0 + rl;
            float mx = -1e30f;
#pragma unroll
            for (int nt = 0; nt < 8; nt++)
#pragma unroll
                for (int rr = 0; rr < 2; rr++) {
                    int jg = jbase + nt * 8 + 2 * cq + rr;
                    float v = (jg <= lim) ? s[nt][half * 2 + rr] : -1e30f;
                    s[nt][half * 2 + rr] = v;
                    mx = fmaxf(mx, v);
                }
            mx = fmaxf(mx, __shfl_xor_sync(0xffffffffu, mx, 1));
            mx = fmaxf(mx, __shfl_xor_sync(0xffffffffu, mx, 2));
            float mnew = fmaxf(m_i[half], mx);
            float corr = exp2f(m_i[half] - mnew);
            m_i[half] = mnew;
            float rs = 0.f;
#pragma unroll
            for (int nt = 0; nt < 8; nt++) {
                float p0 = exp2f(s[nt][half * 2]     - mnew);
                float p1 = exp2f(s[nt][half * 2 + 1] - mnew);
                rs += p0 + p1;
                *(unsigned*)&Ps[rl * 72 + nt * 8 + 2 * cq] = pack_h2(p0, p1);
            }
            rs += __shfl_xor_sync(0xffffffffu, rs, 1);
            rs += __shfl_xor_sync(0xffffffffu, rs, 2);
            l_i[half] = l_i[half] * corr + rs;
#pragma unroll
            for (int nt = 0; nt < 16; nt++) {
                o[nt][half * 2]     *= corr;
                o[nt][half * 2 + 1] *= corr;
            }
        }
        __syncwarp();

#pragma unroll
        for (int kc = 0; kc < 4; kc++) {
            unsigned a[4];
            ldm_x4(a, pmat + kc * 32);
            const uint32_t koff = (uint32_t)kc * (16 * 136 * 2);
#pragma unroll
            for (int ntp = 0; ntp < 8; ntp++) {
                unsigned bf[4];
                ldm_x4t(bf, vmat[buf][ntp] + koff);
                mma_f16(o[2 * ntp],     a[0], a[1], a[2], a[3], bf[0], bf[1]);
                mma_f16(o[2 * ntp + 1], a[0], a[1], a[2], a[3], bf[2], bf[3]);
            }
        }
    }

    // ---- epilogue: fp16 output for out_gemm ----
    float inv0 = 1.0f / l_i[0];
    float inv1 = 1.0f / l_i[1];
    int row0 = q0 + rbase + g;
#pragma unroll
    for (int nt = 0; nt < 16; nt++) {
        int dd = nt * 8 + 2 * cq;
        *(unsigned*)&h_attn[(size_t)row0 * (NH * HD) + h * HD + dd] =
            pack_h2(o[nt][0] * inv0, o[nt][1] * inv0);
        *(unsigned*)&h_attn[(size_t)(row0 + 8) * (NH * HD) + h * HD + dd] =
            pack_h2(o[nt][2] * inv1, o[nt][3] * inv1);
    }
}

// ---------------- launch ----------------
extern "C" void kernel_launch(void* const* d_in, const int* in_sizes, int n_in,
                              void* d_out, int out_size)
{
    (void)in_sizes; (void)n_in; (void)out_size;
    const float* hidden = (const float*)d_in[0];
    const float* Wq     = (const float*)d_in[1];
    const float* Wk     = (const float*)d_in[2];
    const float* Wv     = (const float*)d_in[3];
    const float* Wo     = (const float*)d_in[4];
    const float* past_k = (const float*)d_in[5];
    const float* past_v = (const float*)d_in[6];
    const float* cosT   = (const float*)d_in[7];
    const float* sinT   = (const float*)d_in[8];

    void *p_hh, *p_wq, *p_wk, *p_wv, *p_wo, *p_pk, *p_pv;
    cudaGetSymbolAddress(&p_hh, h_hidden);
    cudaGetSymbolAddress(&p_wq, h_Wq);
    cudaGetSymbolAddress(&p_wk, h_Wk);
    cudaGetSymbolAddress(&p_wv, h_Wv);
    cudaGetSymbolAddress(&p_wo, h_Wo);
    cudaGetSymbolAddress(&p_pk, g_pk);
    cudaGetSymbolAddress(&p_pv, g_pv);

    const int gemm_smem = 18944 * 2;               // 37888 B
    cudaFuncSetAttribute(qkv_gemm, cudaFuncAttributeMaxDynamicSharedMemorySize, gemm_smem);
    cudaFuncSetAttribute(out_gemm, cudaFuncAttributeMaxDynamicSharedMemorySize, gemm_smem);
    const int attn_smem = (34816 + 128 * 72) * 2;  // 88064 B
    cudaFuncSetAttribute(attn_tc, cudaFuncAttributeMaxDynamicSharedMemorySize, attn_smem);

    dim3 blk(256);
    // fp32 -> fp16 conversions
    cvt_kernel<<<(B_Q * DM) / 1024, 256>>>(hidden, (__half*)p_hh);
    cvt_kernel<<<(DM * NH * HD) / 1024, 256>>>(Wq, (__half*)p_wq);
    cvt_kernel<<<(DM * NKV * HD) / 1024, 256>>>(Wk, (__half*)p_wk);
    cvt_kernel<<<(DM * NKV * HD) / 1024, 256>>>(Wv, (__half*)p_wv);
    cvt_kernel<<<(NH * HD * DM) / 1024, 256>>>(Wo, (__half*)p_wo);
    cvt_kernel<<<(NKV * PAST * HD) / 1024, 256>>>(past_k, (__half*)p_pk);
    cvt_kernel<<<(NKV * PAST * HD) / 1024, 256>>>(past_v, (__half*)p_pv);

    qkv_gemm<<<dim3(48, 8), blk, gemm_smem>>>();
    rope_kernel<<<dim3(B_Q, 2 * NKV), 128>>>(cosT, sinT);
    attn_tc<<<dim3(NH, B_Q / 128), blk, attn_smem>>>(cosT, sinT);
    out_gemm<<<dim3(32, 8), blk, gemm_smem>>>((float*)d_out);
}

// round 16
// speedup vs baseline: 3.2255x; 1.0200x over previous
#include <cuda_runtime.h>
#include <cuda_fp16.h>
#include <cstdint>
#include <math.h>

// ---------------- problem constants ----------------
#define B_Q     1024
#define DM      4096
#define NH      32
#define NKV     8
#define HD      128
#define PAST    4096
#define SINKS_N 4
#define QSCALE   0.12751878662109375f   // fl(1/sqrt(128) * log2(e))

// ---------------- scratch ----------------
__device__ float  g_qbuf[B_Q * NH * HD];
__device__ float  g_kbuf[B_Q * NKV * HD];
__device__ float  g_vbuf[B_Q * NKV * HD];
__device__ __half g_kt[NKV * B_Q * HD];
__device__ __half g_vt[NKV * B_Q * HD];
__device__ __half g_pk[NKV * PAST * HD];
__device__ __half g_pv[NKV * PAST * HD];
__device__ __half h_attn[B_Q * NH * HD];
__device__ __half h_hidden[B_Q * DM];
__device__ __half h_Wq[DM * NH * HD];
__device__ __half h_Wk[DM * NKV * HD];
__device__ __half h_Wv[DM * NKV * HD];
__device__ __half h_Wo[NH * HD * DM];

// ---------------- helpers ----------------
__device__ __forceinline__ uint32_t smem_u32(const void* p) {
    uint32_t a;
    asm("{ .reg .u64 t; cvta.to.shared.u64 t, %1; cvt.u32.u64 %0, t; }" : "=r"(a) : "l"(p));
    return a;
}
__device__ __forceinline__ void mma_f16(float d[4],
    unsigned a0, unsigned a1, unsigned a2, unsigned a3, unsigned b0, unsigned b1)
{
    asm volatile(
        "mma.sync.aligned.m16n8k16.row.col.f32.f16.f16.f32 "
        "{%0,%1,%2,%3},{%4,%5,%6,%7},{%8,%9},{%0,%1,%2,%3};"
        : "+f"(d[0]), "+f"(d[1]), "+f"(d[2]), "+f"(d[3])
        : "r"(a0), "r"(a1), "r"(a2), "r"(a3), "r"(b0), "r"(b1));
}
__device__ __forceinline__ void ldm_x4(unsigned a[4], uint32_t addr) {
    asm volatile("ldmatrix.sync.aligned.m8n8.x4.shared.b16 {%0,%1,%2,%3}, [%4];"
        : "=r"(a[0]), "=r"(a[1]), "=r"(a[2]), "=r"(a[3]) : "r"(addr));
}
__device__ __forceinline__ void ldm_x4t(unsigned a[4], uint32_t addr) {
    asm volatile("ldmatrix.sync.aligned.m8n8.x4.trans.shared.b16 {%0,%1,%2,%3}, [%4];"
        : "=r"(a[0]), "=r"(a[1]), "=r"(a[2]), "=r"(a[3]) : "r"(addr));
}
__device__ __forceinline__ unsigned pack_h2(float lo, float hi) {
    __half2 h = __floats2half2_rn(lo, hi);
    return *(unsigned*)&h;
}
#define CP16(dst, src) \
    asm volatile("cp.async.cg.shared.global [%0], [%1], 16;" :: "r"(dst), "l"(src) : "memory")
#define CP_COMMIT() asm volatile("cp.async.commit_group;" ::: "memory")
#define CP_WAIT0()  asm volatile("cp.async.wait_group 0;" ::: "memory")
#define CP_WAIT1()  asm volatile("cp.async.wait_group 1;" ::: "memory")

// ---------------- fused fp32 -> fp16 conversion (one launch, 13M float4) ----------------
__global__ void cvt_all(const float* __restrict__ hidden, const float* __restrict__ Wq,
                        const float* __restrict__ Wk, const float* __restrict__ Wv,
                        const float* __restrict__ Wo, const float* __restrict__ pk,
                        const float* __restrict__ pv)
{
    const size_t S_H  = (size_t)B_Q * DM / 4;         // 1M
    const size_t S_WQ = (size_t)DM * NH * HD / 4;     // 4M
    const size_t S_WK = (size_t)DM * NKV * HD / 4;    // 1M
    const size_t S_PK = (size_t)NKV * PAST * HD / 4;  // 1M

    size_t idx = (size_t)blockIdx.x * 256 + threadIdx.x;
    const float* src; __half* dst; size_t off;
    size_t b = 0;
    if (idx < (b += S_H))        { src = hidden; dst = h_hidden; off = idx - (b - S_H); }
    else if (idx < (b += S_WQ))  { src = Wq;     dst = h_Wq;     off = idx - (b - S_WQ); }
    else if (idx < (b += S_WK))  { src = Wk;     dst = h_Wk;     off = idx - (b - S_WK); }
    else if (idx < (b += S_WK))  { src = Wv;     dst = h_Wv;     off = idx - (b - S_WK); }
    else if (idx < (b += S_WQ))  { src = Wo;     dst = h_Wo;     off = idx - (b - S_WQ); }
    else if (idx < (b += S_PK))  { src = pk;     dst = g_pk;     off = idx - (b - S_PK); }
    else                         { src = pv;     dst = g_pv;     off = idx - b; }

    float4 a = ((const float4*)src)[off];
    *(uint2*)&dst[off * 4] = make_uint2(pack_h2(a.x, a.y), pack_h2(a.z, a.w));
}

// ---------------- fp16 GEMM core: C[.,N] = A[.,K] @ B[K,N] ----------------
// Block 128x128, k-stage 32, 8 warps (2x4), warp tile 64x32.
// 3-stage cp.async pipeline (wait_group 1), ONE barrier per stage.
// A-frags ldm_x4 (stride-40); B-frags ldm_x4t on natural [k][n] (stride-136).
__device__ __forceinline__ void gemm16(
    const __half* __restrict__ A, const __half* __restrict__ B,
    float* __restrict__ C, int N, int K, int m0, int n0, __half* smh)
{
    // stages: A 5120 h each at 0/5120/10240; B 4352 h each after 15360
    const uint32_t sb = smem_u32(smh);
    uint32_t as_u[3], bs_u[3];
#pragma unroll
    for (int i = 0; i < 3; i++) {
        as_u[i] = sb + (uint32_t)(i * 5120) * 2;
        bs_u[i] = sb + (uint32_t)(15360 + i * 4352) * 2;
    }

    const int tid  = threadIdx.x;
    const int w    = tid >> 5, lane = tid & 31;
    const int g    = lane >> 2, cq = lane & 3;
    const int wm   = w & 1, wn = w >> 1;
    const int l7   = lane & 7;

    const int lrow = ((lane >> 3) & 1) * 8 + l7;
    uint32_t aoff[4];
#pragma unroll
    for (int mt = 0; mt < 4; mt++)
        aoff[mt] = (uint32_t)((wm * 64 + mt * 16 + lrow) * 40 + (lane >> 4) * 8) * 2;

    const int bkrow = ((lane >> 3) & 1) * 8 + l7;
    uint32_t boff[2];
#pragma unroll
    for (int ntp = 0; ntp < 2; ntp++)
        boff[ntp] = (uint32_t)(bkrow * 136 + wn * 32 + ntp * 16 + ((lane >> 4) & 1) * 8) * 2;

    float acc[4][4][4];
#pragma unroll
    for (int i = 0; i < 4; i++)
#pragma unroll
        for (int j = 0; j < 4; j++)
#pragma unroll
            for (int r = 0; r < 4; r++) acc[i][j][r] = 0.f;

    const int ns = K >> 5;

#define GEMM_CP(I, BUF) do { \
        const int _k0 = (I) * 32; \
        const uint32_t _ab = as_u[BUF], _bb = bs_u[BUF]; \
        _Pragma("unroll") \
        for (int p = 0; p < 2; p++) { \
            int c = p * 256 + tid; \
            int row = c >> 2, col = (c & 3) * 8; \
            CP16(_ab + (uint32_t)(row * 40 + col) * 2, \
                 &A[(size_t)(m0 + row) * K + _k0 + col]); \
        } \
        _Pragma("unroll") \
        for (int p = 0; p < 2; p++) { \
            int c = p * 256 + tid; \
            int row = c >> 4, col = (c & 15) * 8; \
            CP16(_bb + (uint32_t)(row * 136 + col) * 2, \
                 &B[(size_t)(_k0 + row) * N + n0 + col]); \
        } \
    } while (0)

    GEMM_CP(0, 0); CP_COMMIT();
    GEMM_CP(1, 1); CP_COMMIT();

    int buf = 0;
    for (int i = 0; i < ns; i++) {
        if (i + 1 < ns) CP_WAIT1(); else CP_WAIT0();   // stage i resident
        __syncthreads();   // also: all reads of buffer (i+2)%3 from stage i-1 done

        if (i + 2 < ns) { GEMM_CP(i + 2, (buf + 2 > 2) ? buf - 1 : buf + 2); CP_COMMIT(); }

#pragma unroll
        for (int kc = 0; kc < 2; kc++) {
            unsigned a[4][4];
#pragma unroll
            for (int mt = 0; mt < 4; mt++)
                ldm_x4(a[mt], as_u[buf] + aoff[mt] + kc * 32);
#pragma unroll
            for (int ntp = 0; ntp < 2; ntp++) {
                unsigned bf[4];
                ldm_x4t(bf, bs_u[buf] + boff[ntp] + (uint32_t)kc * (16 * 136 * 2));
#pragma unroll
                for (int mt = 0; mt < 4; mt++) {
                    mma_f16(acc[mt][2 * ntp],     a[mt][0], a[mt][1], a[mt][2], a[mt][3], bf[0], bf[1]);
                    mma_f16(acc[mt][2 * ntp + 1], a[mt][0], a[mt][1], a[mt][2], a[mt][3], bf[2], bf[3]);
                }
            }
        }
        buf = (buf == 2) ? 0 : buf + 1;
    }

#pragma unroll
    for (int mt = 0; mt < 4; mt++)
#pragma unroll
        for (int nt = 0; nt < 4; nt++) {
            int r  = m0 + wm * 64 + mt * 16 + g;
            int cc = n0 + wn * 32 + nt * 8 + 2 * cq;
            *(float2*)&C[(size_t)r * N + cc]       = make_float2(acc[mt][nt][0], acc[mt][nt][1]);
            *(float2*)&C[(size_t)(r + 8) * N + cc] = make_float2(acc[mt][nt][2], acc[mt][nt][3]);
        }
}

__global__ __launch_bounds__(256, 2) void qkv_gemm()
{
    extern __shared__ __half smh[];
    const int bx = blockIdx.x;
    const __half* B; float* C; int N, n0;
    if (bx < 32)      { B = h_Wq; C = g_qbuf; N = NH * HD;  n0 = bx * 128; }
    else if (bx < 40) { B = h_Wk; C = g_kbuf; N = NKV * HD; n0 = (bx - 32) * 128; }
    else              { B = h_Wv; C = g_vbuf; N = NKV * HD; n0 = (bx - 40) * 128; }
    gemm16(h_hidden, B, C, N, DM, blockIdx.y * 128, n0, smh);
}

__global__ __launch_bounds__(256, 2) void out_gemm(float* __restrict__ out)
{
    extern __shared__ __half smh[];
    gemm16(h_attn, h_Wo, out, DM, NH * HD, blockIdx.y * 128, blockIdx.x * 128, smh);
}

// ---------------- RoPE + transpose (K/V only), fp16 outputs ----------------
__global__ void rope_kernel(const float* __restrict__ cosT, const float* __restrict__ sinT)
{
    const int qi   = blockIdx.x;
    const int slot = blockIdx.y;
    const int d    = threadIdx.x;
    const int pos  = PAST + qi;

    if (slot < NKV) {
        const int h = slot;
        const float c = cosT[pos * HD + d];
        const float s = sinT[pos * HD + d];
        const float* src = g_kbuf + (size_t)qi * (NKV * HD) + h * HD;
        float x = src[d], y = src[d ^ 64];
        g_kt[((size_t)h * B_Q + qi) * HD + d] = __float2half_rn(x * c + ((d < 64) ? -y : y) * s);
    } else {
        const int h = slot - NKV;
        g_vt[((size_t)h * B_Q + qi) * HD + d] =
            __float2half_rn(g_vbuf[(size_t)qi * (NKV * HD) + h * HD + d]);
    }
}

// ---------------- Flash attention (R14/R15-verified) ----------------
__global__ __launch_bounds__(256) void attn_tc(
    const float* __restrict__ cosT, const float* __restrict__ sinT)
{
    extern __shared__ __half smh[];
    __half* Ks[2] = { smh,          smh + 8704 };
    __half* Vs[2] = { smh + 17408,  smh + 26112 };
    __half* Ps    = smh + 34816;                    // 128 x 72

    const int tid = threadIdx.x;
    const int w = tid >> 5, lane = tid & 31;
    const int g = lane >> 2, cq = lane & 3;
    const int h  = blockIdx.x;
    const int q0 = (7 - blockIdx.y) * 128;
    const int kvh = h >> 2;
    const int rbase = w * 16;

#pragma unroll
    for (int p = 0; p < 8; p++) {
        int e = p * 256 + tid;
        int row = e >> 4, c8 = (e & 15) * 8;
        const float* src = &g_qbuf[(size_t)(q0 + row) * (NH * HD) + h * HD];
        const int pos = PAST + q0 + row;
        float sgn = (c8 < 64) ? -1.f : 1.f;
        unsigned out[4];
#pragma unroll
        for (int q4 = 0; q4 < 2; q4++) {
            int d4 = c8 + q4 * 4;
            float4 x = *(const float4*)&src[d4];
            float4 y = *(const float4*)&src[d4 ^ 64];
            float4 c = *(const float4*)&cosT[pos * HD + d4];
            float4 s = *(const float4*)&sinT[pos * HD + d4];
            float r0 = (x.x * c.x + sgn * y.x * s.x) * QSCALE;
            float r1 = (x.y * c.y + sgn * y.y * s.y) * QSCALE;
            float r2 = (x.z * c.z + sgn * y.z * s.z) * QSCALE;
            float r3 = (x.w * c.w + sgn * y.w * s.w) * QSCALE;
            out[q4 * 2]     = pack_h2(r0, r1);
            out[q4 * 2 + 1] = pack_h2(r2, r3);
        }
        *(uint4*)&smh[row * 136 + c8] = make_uint4(out[0], out[1], out[2], out[3]);
    }
    __syncthreads();

    const int lrow = rbase + ((lane >> 3) & 1) * 8 + (lane & 7);
    const uint32_t qmat = smem_u32(smh) + (lrow * 136 + (lane >> 4) * 8) * 2;
    unsigned qf[8][4];
#pragma unroll
    for (int kc = 0; kc < 8; kc++)
        ldm_x4(qf[kc], qmat + kc * 32);
    __syncthreads();

    const uint32_t ps_u = smem_u32(Ps);
    const uint32_t pmat = ps_u + (lrow * 72 + (lane >> 4) * 8) * 2;
    const uint32_t ks_u[2] = { smem_u32(Ks[0]), smem_u32(Ks[1]) };
    const uint32_t vs_u[2] = { smem_u32(Vs[0]), smem_u32(Vs[1]) };

    const int l7 = lane & 7;
    uint32_t kmat[2][4], vmat[2][8];
#pragma unroll
    for (int b = 0; b < 2; b++) {
#pragma unroll
        for (int ntp = 0; ntp < 4; ntp++) {
            int row = ntp * 16 + ((lane >> 4) & 1) * 8 + l7;
            kmat[b][ntp] = ks_u[b] + (row * 136 + ((lane >> 3) & 1) * 8) * 2;
        }
#pragma unroll
        for (int ntp = 0; ntp < 8; ntp++) {
            int krow = ((lane >> 3) & 1) * 8 + l7;
            int dcol = ntp * 16 + ((lane >> 4) & 1) * 8;
            vmat[b][ntp] = vs_u[b] + (krow * 136 + dcol) * 2;
        }
    }

    float m_i[2], l_i[2];
    float o[16][4];
    m_i[0] = m_i[1] = -1e30f;
    l_i[0] = l_i[1] = 0.f;
#pragma unroll
    for (int nt = 0; nt < 16; nt++)
#pragma unroll
        for (int r = 0; r < 4; r++) o[nt][r] = 0.f;

    const int ntiles = ((3072 + q0 + 127) >> 6) + 1;

#define CP_KV(KT, BUF) do { \
        const int _jb = (KT) * 64; \
        const uint32_t _kb = ks_u[BUF], _vb = vs_u[BUF]; \
        _Pragma("unroll") \
        for (int p = 0; p < 4; p++) { \
            int c = p * 256 + tid; \
            int row = c >> 4, ch = c & 15; \
            int j = _jb + row; \
            int kp = (j < SINKS_N) ? j : j + 1024; \
            const __half* _ks; const __half* _vs; \
            if (kp < PAST) { \
                size_t off = ((size_t)kvh * PAST + kp) * HD + ch * 8; \
                _ks = &g_pk[off]; _vs = &g_pv[off]; \
            } else { \
                size_t off = ((size_t)kvh * B_Q + (kp - PAST)) * HD + ch * 8; \
                _ks = &g_kt[off]; _vs = &g_vt[off]; \
            } \
            uint32_t doff = (uint32_t)(row * 136 + ch * 8) * 2; \
            CP16(_kb + doff, _ks); \
            CP16(_vb + doff, _vs); \
        } \
    } while (0)

    CP_KV(0, 0);
    CP_COMMIT();

    for (int kt = 0; kt < ntiles; kt++) {
        const int jbase = kt * 64;
        const int buf = kt & 1;
        const bool pf = (kt + 1 < ntiles);

        CP_WAIT0();
        __syncthreads();

        if (pf) { CP_KV(kt + 1, buf ^ 1); CP_COMMIT(); }

        float s[8][4];
#pragma unroll
        for (int nt = 0; nt < 8; nt++)
#pragma unroll
            for (int r = 0; r < 4; r++) s[nt][r] = 0.f;

#pragma unroll
        for (int kc = 0; kc < 8; kc++) {
#pragma unroll
            for (int ntp = 0; ntp < 4; ntp++) {
                unsigned bf[4];
                ldm_x4(bf, kmat[buf][ntp] + kc * 32);
                mma_f16(s[2 * ntp],     qf[kc][0], qf[kc][1], qf[kc][2], qf[kc][3], bf[0], bf[1]);
                mma_f16(s[2 * ntp + 1], qf[kc][0], qf[kc][1], qf[kc][2], qf[kc][3], bf[2], bf[3]);
            }
        }

#pragma unroll
        for (int half = 0; half < 2; half++) {
            const int rl  = rbase + g + half * 8;
            const int lim = 3072 + q0 + rl;
            float mx = -1e30f;
#pragma unroll
            for (int nt = 0; nt < 8; nt++)
#pragma unroll
                for (int rr = 0; rr < 2; rr++) {
                    int jg = jbase + nt * 8 + 2 * cq + rr;
                    float v = (jg <= lim) ? s[nt][half * 2 + rr] : -1e30f;
                    s[nt][half * 2 + rr] = v;
                    mx = fmaxf(mx, v);
                }
            mx = fmaxf(mx, __shfl_xor_sync(0xffffffffu, mx, 1));
            mx = fmaxf(mx, __shfl_xor_sync(0xffffffffu, mx, 2));
            float mnew = fmaxf(m_i[half], mx);
            float corr = exp2f(m_i[half] - mnew);
            m_i[half] = mnew;
            float rs = 0.f;
#pragma unroll
            for (int nt = 0; nt < 8; nt++) {
                float p0 = exp2f(s[nt][half * 2]     - mnew);
                float p1 = exp2f(s[nt][half * 2 + 1] - mnew);
                rs += p0 + p1;
                *(unsigned*)&Ps[rl * 72 + nt * 8 + 2 * cq] = pack_h2(p0, p1);
            }
            rs += __shfl_xor_sync(0xffffffffu, rs, 1);
            rs += __shfl_xor_sync(0xffffffffu, rs, 2);
            l_i[half] = l_i[half] * corr + rs;
#pragma unroll
            for (int nt = 0; nt < 16; nt++) {
                o[nt][half * 2]     *= corr;
                o[nt][half * 2 + 1] *= corr;
            }
        }
        __syncwarp();

#pragma unroll
        for (int kc = 0; kc < 4; kc++) {
            unsigned a[4];
            ldm_x4(a, pmat + kc * 32);
            const uint32_t koff = (uint32_t)kc * (16 * 136 * 2);
#pragma unroll
            for (int ntp = 0; ntp < 8; ntp++) {
                unsigned bf[4];
                ldm_x4t(bf, vmat[buf][ntp] + koff);
                mma_f16(o[2 * ntp],     a[0], a[1], a[2], a[3], bf[0], bf[1]);
                mma_f16(o[2 * ntp + 1], a[0], a[1], a[2], a[3], bf[2], bf[3]);
            }
        }
    }

    float inv0 = 1.0f / l_i[0];
    float inv1 = 1.0f / l_i[1];
    int row0 = q0 + rbase + g;
#pragma unroll
    for (int nt = 0; nt < 16; nt++) {
        int dd = nt * 8 + 2 * cq;
        *(unsigned*)&h_attn[(size_t)row0 * (NH * HD) + h * HD + dd] =
            pack_h2(o[nt][0] * inv0, o[nt][1] * inv0);
        *(unsigned*)&h_attn[(size_t)(row0 + 8) * (NH * HD) + h * HD + dd] =
            pack_h2(o[nt][2] * inv1, o[nt][3] * inv1);
    }
}

// ---------------- launch ----------------
extern "C" void kernel_launch(void* const* d_in, const int* in_sizes, int n_in,
                              void* d_out, int out_size)
{
    (void)in_sizes; (void)n_in; (void)out_size;
    const float* hidden = (const float*)d_in[0];
    const float* Wq     = (const float*)d_in[1];
    const float* Wk     = (const float*)d_in[2];
    const float* Wv     = (const float*)d_in[3];
    const float* Wo     = (const float*)d_in[4];
    const float* past_k = (const float*)d_in[5];
    const float* past_v = (const float*)d_in[6];
    const float* cosT   = (const float*)d_in[7];
    const float* sinT   = (const float*)d_in[8];

    const int gemm_smem = 28416 * 2;               // 56832 B (3-stage)
    cudaFuncSetAttribute(qkv_gemm, cudaFuncAttributeMaxDynamicSharedMemorySize, gemm_smem);
    cudaFuncSetAttribute(out_gemm, cudaFuncAttributeMaxDynamicSharedMemorySize, gemm_smem);
    const int attn_smem = (34816 + 128 * 72) * 2;  // 88064 B
    cudaFuncSetAttribute(attn_tc, cudaFuncAttributeMaxDynamicSharedMemorySize, attn_smem);

    dim3 blk(256);
    // fused fp32 -> fp16 conversion: 13M float4 total
    const size_t total_f4 = (size_t)B_Q * DM / 4 + 2 * (size_t)DM * NH * HD / 4 +
                            2 * (size_t)DM * NKV * HD / 4 + 2 * (size_t)NKV * PAST * HD / 4;
    cvt_all<<<(unsigned)(total_f4 / 256), 256>>>(hidden, Wq, Wk, Wv, Wo, past_k, past_v);

    qkv_gemm<<<dim3(48, 8), blk, gemm_smem>>>();
    rope_kernel<<<dim3(B_Q, 2 * NKV), 128>>>(cosT, sinT);
    attn_tc<<<dim3(NH, B_Q / 128), blk, attn_smem>>>(cosT, sinT);
    out_gemm<<<dim3(32, 8), blk, gemm_smem>>>((float*)d_out);
}

// round 17
// speedup vs baseline: 3.2959x; 1.0218x over previous
#include <cuda_runtime.h>
#include <cuda_fp16.h>
#include <cstdint>
#include <math.h>

// ---------------- problem constants ----------------
#define B_Q     1024
#define DM      4096
#define NH      32
#define NKV     8
#define HD      128
#define PAST    4096
#define SINKS_N 4
#define QSCALE   0.12751878662109375f   // fl(1/sqrt(128) * log2(e))

// ---------------- scratch ----------------
__device__ float  g_qbuf[B_Q * NH * HD];
__device__ float  g_kbuf[B_Q * NKV * HD];
__device__ float  g_vbuf[B_Q * NKV * HD];
__device__ __half g_kt[NKV * B_Q * HD];
__device__ __half g_vt[NKV * B_Q * HD];
__device__ __half g_pk[NKV * PAST * HD];
__device__ __half g_pv[NKV * PAST * HD];
__device__ __half h_attn[B_Q * NH * HD];
__device__ __half h_hidden[B_Q * DM];
__device__ __half h_Wq[DM * NH * HD];
__device__ __half h_Wk[DM * NKV * HD];
__device__ __half h_Wv[DM * NKV * HD];
__device__ __half h_Wo[NH * HD * DM];

// ---------------- helpers ----------------
__device__ __forceinline__ uint32_t smem_u32(const void* p) {
    uint32_t a;
    asm("{ .reg .u64 t; cvta.to.shared.u64 t, %1; cvt.u32.u64 %0, t; }" : "=r"(a) : "l"(p));
    return a;
}
__device__ __forceinline__ void mma_f16(float d[4],
    unsigned a0, unsigned a1, unsigned a2, unsigned a3, unsigned b0, unsigned b1)
{
    asm volatile(
        "mma.sync.aligned.m16n8k16.row.col.f32.f16.f16.f32 "
        "{%0,%1,%2,%3},{%4,%5,%6,%7},{%8,%9},{%0,%1,%2,%3};"
        : "+f"(d[0]), "+f"(d[1]), "+f"(d[2]), "+f"(d[3])
        : "r"(a0), "r"(a1), "r"(a2), "r"(a3), "r"(b0), "r"(b1));
}
__device__ __forceinline__ void ldm_x4(unsigned a[4], uint32_t addr) {
    asm volatile("ldmatrix.sync.aligned.m8n8.x4.shared.b16 {%0,%1,%2,%3}, [%4];"
        : "=r"(a[0]), "=r"(a[1]), "=r"(a[2]), "=r"(a[3]) : "r"(addr));
}
__device__ __forceinline__ void ldm_x4t(unsigned a[4], uint32_t addr) {
    asm volatile("ldmatrix.sync.aligned.m8n8.x4.trans.shared.b16 {%0,%1,%2,%3}, [%4];"
        : "=r"(a[0]), "=r"(a[1]), "=r"(a[2]), "=r"(a[3]) : "r"(addr));
}
__device__ __forceinline__ unsigned pack_h2(float lo, float hi) {
    __half2 h = __floats2half2_rn(lo, hi);
    return *(unsigned*)&h;
}
#define CP16(dst, src) \
    asm volatile("cp.async.cg.shared.global [%0], [%1], 16;" :: "r"(dst), "l"(src) : "memory")
#define CP_COMMIT() asm volatile("cp.async.commit_group;" ::: "memory")
#define CP_WAIT0()  asm volatile("cp.async.wait_group 0;" ::: "memory")
#define CP_WAIT1()  asm volatile("cp.async.wait_group 1;" ::: "memory")

// ---------------- fused fp32 -> fp16 conversion ----------------
__global__ void cvt_all(const float* __restrict__ hidden, const float* __restrict__ Wq,
                        const float* __restrict__ Wk, const float* __restrict__ Wv,
                        const float* __restrict__ Wo, const float* __restrict__ pk,
                        const float* __restrict__ pv)
{
    const size_t S_H  = (size_t)B_Q * DM / 4;
    const size_t S_WQ = (size_t)DM * NH * HD / 4;
    const size_t S_WK = (size_t)DM * NKV * HD / 4;
    const size_t S_PK = (size_t)NKV * PAST * HD / 4;

    size_t idx = (size_t)blockIdx.x * 256 + threadIdx.x;
    const float* src; __half* dst; size_t off;
    size_t b = 0;
    if (idx < (b += S_H))        { src = hidden; dst = h_hidden; off = idx - (b - S_H); }
    else if (idx < (b += S_WQ))  { src = Wq;     dst = h_Wq;     off = idx - (b - S_WQ); }
    else if (idx < (b += S_WK))  { src = Wk;     dst = h_Wk;     off = idx - (b - S_WK); }
    else if (idx < (b += S_WK))  { src = Wv;     dst = h_Wv;     off = idx - (b - S_WK); }
    else if (idx < (b += S_WQ))  { src = Wo;     dst = h_Wo;     off = idx - (b - S_WQ); }
    else if (idx < (b += S_PK))  { src = pk;     dst = g_pk;     off = idx - (b - S_PK); }
    else                         { src = pv;     dst = g_pv;     off = idx - b; }

    float4 a = ((const float4*)src)[off];
    *(uint2*)&dst[off * 4] = make_uint2(pack_h2(a.x, a.y), pack_h2(a.z, a.w));
}

// ---------------- fp16 GEMM core (R16-verified, frozen) ----------------
__device__ __forceinline__ void gemm16(
    const __half* __restrict__ A, const __half* __restrict__ B,
    float* __restrict__ C, int N, int K, int m0, int n0, __half* smh)
{
    const uint32_t sb = smem_u32(smh);
    uint32_t as_u[3], bs_u[3];
#pragma unroll
    for (int i = 0; i < 3; i++) {
        as_u[i] = sb + (uint32_t)(i * 5120) * 2;
        bs_u[i] = sb + (uint32_t)(15360 + i * 4352) * 2;
    }

    const int tid  = threadIdx.x;
    const int w    = tid >> 5, lane = tid & 31;
    const int g    = lane >> 2, cq = lane & 3;
    const int wm   = w & 1, wn = w >> 1;
    const int l7   = lane & 7;

    const int lrow = ((lane >> 3) & 1) * 8 + l7;
    uint32_t aoff[4];
#pragma unroll
    for (int mt = 0; mt < 4; mt++)
        aoff[mt] = (uint32_t)((wm * 64 + mt * 16 + lrow) * 40 + (lane >> 4) * 8) * 2;

    const int bkrow = ((lane >> 3) & 1) * 8 + l7;
    uint32_t boff[2];
#pragma unroll
    for (int ntp = 0; ntp < 2; ntp++)
        boff[ntp] = (uint32_t)(bkrow * 136 + wn * 32 + ntp * 16 + ((lane >> 4) & 1) * 8) * 2;

    float acc[4][4][4];
#pragma unroll
    for (int i = 0; i < 4; i++)
#pragma unroll
        for (int j = 0; j < 4; j++)
#pragma unroll
            for (int r = 0; r < 4; r++) acc[i][j][r] = 0.f;

    const int ns = K >> 5;

#define GEMM_CP(I, BUF) do { \
        const int _k0 = (I) * 32; \
        const uint32_t _ab = as_u[BUF], _bb = bs_u[BUF]; \
        _Pragma("unroll") \
        for (int p = 0; p < 2; p++) { \
            int c = p * 256 + tid; \
            int row = c >> 2, col = (c & 3) * 8; \
            CP16(_ab + (uint32_t)(row * 40 + col) * 2, \
                 &A[(size_t)(m0 + row) * K + _k0 + col]); \
        } \
        _Pragma("unroll") \
        for (int p = 0; p < 2; p++) { \
            int c = p * 256 + tid; \
            int row = c >> 4, col = (c & 15) * 8; \
            CP16(_bb + (uint32_t)(row * 136 + col) * 2, \
                 &B[(size_t)(_k0 + row) * N + n0 + col]); \
        } \
    } while (0)

    GEMM_CP(0, 0); CP_COMMIT();
    GEMM_CP(1, 1); CP_COMMIT();

    int buf = 0;
    for (int i = 0; i < ns; i++) {
        if (i + 1 < ns) CP_WAIT1(); else CP_WAIT0();
        __syncthreads();

        if (i + 2 < ns) { GEMM_CP(i + 2, (buf + 2 > 2) ? buf - 1 : buf + 2); CP_COMMIT(); }

#pragma unroll
        for (int kc = 0; kc < 2; kc++) {
            unsigned a[4][4];
#pragma unroll
            for (int mt = 0; mt < 4; mt++)
                ldm_x4(a[mt], as_u[buf] + aoff[mt] + kc * 32);
#pragma unroll
            for (int ntp = 0; ntp < 2; ntp++) {
                unsigned bf[4];
                ldm_x4t(bf, bs_u[buf] + boff[ntp] + (uint32_t)kc * (16 * 136 * 2));
#pragma unroll
                for (int mt = 0; mt < 4; mt++) {
                    mma_f16(acc[mt][2 * ntp],     a[mt][0], a[mt][1], a[mt][2], a[mt][3], bf[0], bf[1]);
                    mma_f16(acc[mt][2 * ntp + 1], a[mt][0], a[mt][1], a[mt][2], a[mt][3], bf[2], bf[3]);
                }
            }
        }
        buf = (buf == 2) ? 0 : buf + 1;
    }

#pragma unroll
    for (int mt = 0; mt < 4; mt++)
#pragma unroll
        for (int nt = 0; nt < 4; nt++) {
            int r  = m0 + wm * 64 + mt * 16 + g;
            int cc = n0 + wn * 32 + nt * 8 + 2 * cq;
            *(float2*)&C[(size_t)r * N + cc]       = make_float2(acc[mt][nt][0], acc[mt][nt][1]);
            *(float2*)&C[(size_t)(r + 8) * N + cc] = make_float2(acc[mt][nt][2], acc[mt][nt][3]);
        }
}

__global__ __launch_bounds__(256, 2) void qkv_gemm()
{
    extern __shared__ __half smh[];
    const int bx = blockIdx.x;
    const __half* B; float* C; int N, n0;
    if (bx < 32)      { B = h_Wq; C = g_qbuf; N = NH * HD;  n0 = bx * 128; }
    else if (bx < 40) { B = h_Wk; C = g_kbuf; N = NKV * HD; n0 = (bx - 32) * 128; }
    else              { B = h_Wv; C = g_vbuf; N = NKV * HD; n0 = (bx - 40) * 128; }
    gemm16(h_hidden, B, C, N, DM, blockIdx.y * 128, n0, smh);
}

__global__ __launch_bounds__(256, 2) void out_gemm(float* __restrict__ out)
{
    extern __shared__ __half smh[];
    gemm16(h_attn, h_Wo, out, DM, NH * HD, blockIdx.y * 128, blockIdx.x * 128, smh);
}

// ---------------- RoPE + transpose (K/V only), fp16 outputs ----------------
__global__ void rope_kernel(const float* __restrict__ cosT, const float* __restrict__ sinT)
{
    const int qi   = blockIdx.x;
    const int slot = blockIdx.y;
    const int d    = threadIdx.x;
    const int pos  = PAST + qi;

    if (slot < NKV) {
        const int h = slot;
        const float c = cosT[pos * HD + d];
        const float s = sinT[pos * HD + d];
        const float* src = g_kbuf + (size_t)qi * (NKV * HD) + h * HD;
        float x = src[d], y = src[d ^ 64];
        g_kt[((size_t)h * B_Q + qi) * HD + d] = __float2half_rn(x * c + ((d < 64) ? -y : y) * s);
    } else {
        const int h = slot - NKV;
        g_vt[((size_t)h * B_Q + qi) * HD + d] =
            __float2half_rn(g_vbuf[(size_t)qi * (NKV * HD) + h * HD + d]);
    }
}

// ---------------- Flash attention: fp16 mma, K-tile 128 ----------------
// 256 threads = 8 warps. Q-tile 128 (warp w: rows w*16..+15), K-tile 128.
// Halved softmax/barrier fixed costs vs K-tile 64. Double-buffered cp.async.
// Smem (halves): Ks0/Ks1 128x136 @0/17408, Vs0/Vs1 @34816/52224, Ps 128x136 @69632.
__global__ __launch_bounds__(256) void attn_tc(
    const float* __restrict__ cosT, const float* __restrict__ sinT)
{
    extern __shared__ __half smh[];
    const uint32_t sb = smem_u32(smh);
    const uint32_t ks_u[2] = { sb,                sb + 17408u * 2 };
    const uint32_t vs_u[2] = { sb + 34816u * 2,   sb + 52224u * 2 };
    __half* Ps = smh + 69632;                    // 128 x 136

    const int tid = threadIdx.x;
    const int w = tid >> 5, lane = tid & 31;
    const int g = lane >> 2, cq = lane & 3;
    const int h  = blockIdx.x;
    const int q0 = (7 - blockIdx.y) * 128;
    const int kvh = h >> 2;
    const int rbase = w * 16;

    // ---- stage Q (fp16, stride 136) with fused RoPE + QSCALE over Ks0 region ----
#pragma unroll
    for (int p = 0; p < 8; p++) {
        int e = p * 256 + tid;
        int row = e >> 4, c8 = (e & 15) * 8;
        const float* src = &g_qbuf[(size_t)(q0 + row) * (NH * HD) + h * HD];
        const int pos = PAST + q0 + row;
        float sgn = (c8 < 64) ? -1.f : 1.f;
        unsigned out[4];
#pragma unroll
        for (int q4 = 0; q4 < 2; q4++) {
            int d4 = c8 + q4 * 4;
            float4 x = *(const float4*)&src[d4];
            float4 y = *(const float4*)&src[d4 ^ 64];
            float4 c = *(const float4*)&cosT[pos * HD + d4];
            float4 s = *(const float4*)&sinT[pos * HD + d4];
            float r0 = (x.x * c.x + sgn * y.x * s.x) * QSCALE;
            float r1 = (x.y * c.y + sgn * y.y * s.y) * QSCALE;
            float r2 = (x.z * c.z + sgn * y.z * s.z) * QSCALE;
            float r3 = (x.w * c.w + sgn * y.w * s.w) * QSCALE;
            out[q4 * 2]     = pack_h2(r0, r1);
            out[q4 * 2 + 1] = pack_h2(r2, r3);
        }
        *(uint4*)&smh[row * 136 + c8] = make_uint4(out[0], out[1], out[2], out[3]);
    }
    __syncthreads();

    const int lrow = rbase + ((lane >> 3) & 1) * 8 + (lane & 7);
    const uint32_t qmat = sb + (lrow * 136 + (lane >> 4) * 8) * 2;
    unsigned qf[8][4];
#pragma unroll
    for (int kc = 0; kc < 8; kc++)
        ldm_x4(qf[kc], qmat + kc * 32);
    __syncthreads();   // Q staging reads done before cp.async overwrites Ks0

    const uint32_t pmat = smem_u32(Ps) + (lrow * 136 + (lane >> 4) * 8) * 2;

    const int l7 = lane & 7;
    uint32_t kmat[2][8], vmat[2][8];
#pragma unroll
    for (int b = 0; b < 2; b++) {
#pragma unroll
        for (int ntp = 0; ntp < 8; ntp++) {
            int row = ntp * 16 + ((lane >> 4) & 1) * 8 + l7;
            kmat[b][ntp] = ks_u[b] + (row * 136 + ((lane >> 3) & 1) * 8) * 2;
        }
#pragma unroll
        for (int ntp = 0; ntp < 8; ntp++) {
            int krow = ((lane >> 3) & 1) * 8 + l7;
            int dcol = ntp * 16 + ((lane >> 4) & 1) * 8;
            vmat[b][ntp] = vs_u[b] + (krow * 136 + dcol) * 2;
        }
    }

    float m_i[2], l_i[2];
    float o[16][4];
    m_i[0] = m_i[1] = -1e30f;
    l_i[0] = l_i[1] = 0.f;
#pragma unroll
    for (int nt = 0; nt < 16; nt++)
#pragma unroll
        for (int r = 0; r < 4; r++) o[nt][r] = 0.f;

    const int ntiles = ((3072 + q0 + 127) >> 7) + 1;

    // cp.async: 8 chunks each for K and V per thread per 128-key tile
#define CP_KV(KT, BUF) do { \
        const int _jb = (KT) * 128; \
        const uint32_t _kb = ks_u[BUF], _vb = vs_u[BUF]; \
        _Pragma("unroll") \
        for (int p = 0; p < 8; p++) { \
            int c = p * 256 + tid; \
            int row = c >> 4, ch = c & 15; \
            int j = _jb + row; \
            int kp = (j < SINKS_N) ? j : j + 1024; \
            const __half* _ks; const __half* _vs; \
            if (kp < PAST) { \
                size_t off = ((size_t)kvh * PAST + kp) * HD + ch * 8; \
                _ks = &g_pk[off]; _vs = &g_pv[off]; \
            } else { \
                size_t off = ((size_t)kvh * B_Q + (kp - PAST)) * HD + ch * 8; \
                _ks = &g_kt[off]; _vs = &g_vt[off]; \
            } \
            uint32_t doff = (uint32_t)(row * 136 + ch * 8) * 2; \
            CP16(_kb + doff, _ks); \
            CP16(_vb + doff, _vs); \
        } \
    } while (0)

    CP_KV(0, 0);
    CP_COMMIT();

    for (int kt = 0; kt < ntiles; kt++) {
        const int jbase = kt * 128;
        const int buf = kt & 1;
        const bool pf = (kt + 1 < ntiles);

        CP_WAIT0();
        __syncthreads();

        if (pf) { CP_KV(kt + 1, buf ^ 1); CP_COMMIT(); }

        // ---- S = Q @ K^T : 16 rows x 128 keys per warp ----
        float s[16][4];
#pragma unroll
        for (int nt = 0; nt < 16; nt++)
#pragma unroll
            for (int r = 0; r < 4; r++) s[nt][r] = 0.f;

#pragma unroll
        for (int kc = 0; kc < 8; kc++) {
#pragma unroll
            for (int ntp = 0; ntp < 8; ntp++) {
                unsigned bf[4];
                ldm_x4(bf, kmat[buf][ntp] + kc * 32);
                mma_f16(s[2 * ntp],     qf[kc][0], qf[kc][1], qf[kc][2], qf[kc][3], bf[0], bf[1]);
                mma_f16(s[2 * ntp + 1], qf[kc][0], qf[kc][1], qf[kc][2], qf[kc][3], bf[2], bf[3]);
            }
        }

        // ---- online softmax (base-2 domain) ----
#pragma unroll
        for (int half = 0; half < 2; half++) {
            const int rl  = rbase + g + half * 8;
            const int lim = 3072 + q0 + rl;
            float mx = -1e30f;
#pragma unroll
            for (int nt = 0; nt < 16; nt++)
#pragma unroll
                for (int rr = 0; rr < 2; rr++) {
                    int jg = jbase + nt * 8 + 2 * cq + rr;
                    float v = (jg <= lim) ? s[nt][half * 2 + rr] : -1e30f;
                    s[nt][half * 2 + rr] = v;
                    mx = fmaxf(mx, v);
                }
            mx = fmaxf(mx, __shfl_xor_sync(0xffffffffu, mx, 1));
            mx = fmaxf(mx, __shfl_xor_sync(0xffffffffu, mx, 2));
            float mnew = fmaxf(m_i[half], mx);
            float corr = exp2f(m_i[half] - mnew);
            m_i[half] = mnew;
            float rs = 0.f;
#pragma unroll
            for (int nt = 0; nt < 16; nt++) {
                float p0 = exp2f(s[nt][half * 2]     - mnew);
                float p1 = exp2f(s[nt][half * 2 + 1] - mnew);
                rs += p0 + p1;
                *(unsigned*)&Ps[rl * 136 + nt * 8 + 2 * cq] = pack_h2(p0, p1);
            }
            rs += __shfl_xor_sync(0xffffffffu, rs, 1);
            rs += __shfl_xor_sync(0xffffffffu, rs, 2);
            l_i[half] = l_i[half] * corr + rs;
#pragma unroll
            for (int nt = 0; nt < 16; nt++) {
                o[nt][half * 2]     *= corr;
                o[nt][half * 2 + 1] *= corr;
            }
        }
        __syncwarp();   // Ps is warp-private

        // ---- O += P @ V : 16 rows x 128 d per warp, 8 k16-chunks ----
#pragma unroll
        for (int kc = 0; kc < 8; kc++) {
            unsigned a[4];
            ldm_x4(a, pmat + kc * 32);
            const uint32_t koff = (uint32_t)kc * (16 * 136 * 2);
#pragma unroll
            for (int ntp = 0; ntp < 8; ntp++) {
                unsigned bf[4];
                ldm_x4t(bf, vmat[buf][ntp] + koff);
                mma_f16(o[2 * ntp],     a[0], a[1], a[2], a[3], bf[0], bf[1]);
                mma_f16(o[2 * ntp + 1], a[0], a[1], a[2], a[3], bf[2], bf[3]);
            }
        }
    }

    // ---- epilogue: fp16 output for out_gemm ----
    float inv0 = 1.0f / l_i[0];
    float inv1 = 1.0f / l_i[1];
    int row0 = q0 + rbase + g;
#pragma unroll
    for (int nt = 0; nt < 16; nt++) {
        int dd = nt * 8 + 2 * cq;
        *(unsigned*)&h_attn[(size_t)row0 * (NH * HD) + h * HD + dd] =
            pack_h2(o[nt][0] * inv0, o[nt][1] * inv0);
        *(unsigned*)&h_attn[(size_t)(row0 + 8) * (NH * HD) + h * HD + dd] =
            pack_h2(o[nt][2] * inv1, o[nt][3] * inv1);
    }
}

// ---------------- launch ----------------
extern "C" void kernel_launch(void* const* d_in, const int* in_sizes, int n_in,
                              void* d_out, int out_size)
{
    (void)in_sizes; (void)n_in; (void)out_size;
    const float* hidden = (const float*)d_in[0];
    const float* Wq     = (const float*)d_in[1];
    const float* Wk     = (const float*)d_in[2];
    const float* Wv     = (const float*)d_in[3];
    const float* Wo     = (const float*)d_in[4];
    const float* past_k = (const float*)d_in[5];
    const float* past_v = (const float*)d_in[6];
    const float* cosT   = (const float*)d_in[7];
    const float* sinT   = (const float*)d_in[8];

    const int gemm_smem = 28416 * 2;               // 56832 B (3-stage)
    cudaFuncSetAttribute(qkv_gemm, cudaFuncAttributeMaxDynamicSharedMemorySize, gemm_smem);
    cudaFuncSetAttribute(out_gemm, cudaFuncAttributeMaxDynamicSharedMemorySize, gemm_smem);
    const int attn_smem = (69632 + 17408) * 2;     // 174080 B
    cudaFuncSetAttribute(attn_tc, cudaFuncAttributeMaxDynamicSharedMemorySize, attn_smem);

    dim3 blk(256);
    const size_t total_f4 = (size_t)B_Q * DM / 4 + 2 * (size_t)DM * NH * HD / 4 +
                            2 * (size_t)DM * NKV * HD / 4 + 2 * (size_t)NKV * PAST * HD / 4;
    cvt_all<<<(unsigned)(total_f4 / 256), 256>>>(hidden, Wq, Wk, Wv, Wo, past_k, past_v);

    qkv_gemm<<<dim3(48, 8), blk, gemm_smem>>>();
    rope_kernel<<<dim3(B_Q, 2 * NKV), 128>>>(cosT, sinT);
    attn_tc<<<dim3(NH, B_Q / 128), blk, attn_smem>>>(cosT, sinT);
    out_gemm<<<dim3(32, 8), blk, gemm_smem>>>((float*)d_out);
}